// round 13
// baseline (speedup 1.0000x reference)
#include <cuda_runtime.h>
#include <math.h>

#define NLM 25
#define NPATH 65
#define PI_F 3.14159265358979323846f
#define CUTOFF_F 5.0f
#define MAXN 10240

// ---------------- scratch ----------------
__device__ float g_y0[MAXN * NLM * 16];
__device__ float g_y1[MAXN * 2 * NLM * 64];
__device__ float g_y2[MAXN * 2 * NLM * 64];

__constant__ int c_deg[NLM] = {0,1,1,1,2,2,2,2,2,3,3,3,3,3,3,3,4,4,4,4,4,4,4,4,4};

// ================= compile-time CG construction =================
constexpr double CFACT[16] = {1.0,1.0,2.0,6.0,24.0,120.0,720.0,5040.0,40320.0,
                              362880.0,3628800.0,39916800.0,479001600.0,
                              6227020800.0,87178291200.0,1307674368000.0};

constexpr double csqrt_ct(double x) {
    if (x <= 0.0) return 0.0;
    double g = 1.0, t = x;
    while (t > 4.0) { t *= 0.25; g *= 2.0; }
    while (t < 0.25) { t *= 4.0; g *= 0.5; }
    double y = g * (0.5 + 0.5 * t);
    for (int i = 0; i < 10; i++) y = 0.5 * (y + x / y);
    return y;
}

constexpr int cdeg_ct(int i) { return i < 1 ? 0 : i < 4 ? 1 : i < 9 ? 2 : i < 16 ? 3 : 4; }

constexpr double cg_complex_ct(int l1,int m1,int l2,int m2,int l3,int m3) {
    if (m1 + m2 != m3) return 0.0;
    int lo = l1 > l2 ? l1 - l2 : l2 - l1;
    if (l3 < lo || l3 > l1 + l2) return 0.0;
    double P = CFACT[l1+l2-l3] * CFACT[l1-l2+l3] * CFACT[-l1+l2+l3] / CFACT[l1+l2+l3+1]
             * CFACT[l1+m1] * CFACT[l1-m1] * CFACT[l2+m2] * CFACT[l2-m2]
             * CFACT[l3+m3] * CFACT[l3-m3];
    double sp = csqrt_ct(P);
    int kmin = 0;
    if (l2 - l3 - m1 > kmin) kmin = l2 - l3 - m1;
    if (l1 - l3 + m2 > kmin) kmin = l1 - l3 + m2;
    int kmax = l1 + l2 - l3;
    if (l1 - m1 < kmax) kmax = l1 - m1;
    if (l2 + m2 < kmax) kmax = l2 + m2;
    double s = 0.0;
    for (int k = kmin; k <= kmax; k++) {
        double D = CFACT[k] * CFACT[l1+l2-l3-k] * CFACT[l1-m1-k] * CFACT[l2+m2-k]
                 * CFACT[l3-l2+m1+k] * CFACT[l3-l1-m2+k];
        s += ((k & 1) ? -1.0 : 1.0) * sp / D;
    }
    return csqrt_ct(2.0 * l3 + 1.0) * s;
}

struct DArr { double v[NLM * NLM * NLM]; };
constexpr DArr build_cc() {
    DArr A{};
    for (int l1 = 0; l1 <= 4; l1++)
    for (int m1 = -l1; m1 <= l1; m1++)
    for (int l2 = 0; l2 <= 4; l2++)
    for (int m2 = -l2; m2 <= l2; m2++) {
        int lo = l1 > l2 ? l1 - l2 : l2 - l1;
        int hi = (l1 + l2 > 4) ? 4 : (l1 + l2);
        for (int l3 = lo; l3 <= hi; l3++) {
            int m3 = m1 + m2;
            if (m3 >= -l3 && m3 <= l3)
                A.v[((l1*l1+l1+m1)*NLM + (l2*l2+l2+m2))*NLM + (l3*l3+l3+m3)]
                    = cg_complex_ct(l1, m1, l2, m2, l3, m3);
        }
    }
    return A;
}
constexpr DArr CC = build_cc();

struct URct { int col[2]; double re[2], im[2]; int n; };
constexpr URct u_row_ct(int l, int m) {
    URct u{};
    int off = l * l + l;
    const double is2 = 0.7071067811865476;
    if (m == 0) { u.col[0] = off; u.re[0] = 1.0; u.im[0] = 0.0; u.n = 1; return u; }
    if (m > 0) {
        double sgn = (m & 1) ? -1.0 : 1.0;
        u.col[0] = off + m; u.re[0] = sgn * is2; u.im[0] = 0.0;
        u.col[1] = off - m; u.re[1] = is2;       u.im[1] = 0.0;
        u.n = 2; return u;
    }
    int mm = -m;
    double sgn = (mm & 1) ? -1.0 : 1.0;
    u.col[0] = off - mm; u.re[0] = 0.0; u.im[0] = is2;
    u.col[1] = off + mm; u.re[1] = 0.0; u.im[1] = -sgn * is2;
    u.n = 2;
    return u;
}

constexpr float realCG(int i, int j, int k) {
    int li = cdeg_ct(i), mi = i - li*li - li;
    int lj = cdeg_ct(j), mj = j - lj*lj - lj;
    int lk = cdeg_ct(k), mk = k - lk*lk - lk;
    URct ua = u_row_ct(li, mi), ub = u_row_ct(lj, mj), uc = u_row_ct(lk, mk);
    double tre = 0.0, tim = 0.0;
    for (int aa = 0; aa < ua.n; aa++)
      for (int bb = 0; bb < ub.n; bb++) {
        double wre = ua.re[aa]*ub.re[bb] - ua.im[aa]*ub.im[bb];
        double wim = ua.re[aa]*ub.im[bb] + ua.im[aa]*ub.re[bb];
        for (int ci = 0; ci < uc.n; ci++) {
            double cv = CC.v[(ua.col[aa]*NLM + ub.col[bb])*NLM + uc.col[ci]];
            if (cv == 0.0) continue;
            double ur3 = uc.re[ci], ui3 = -uc.im[ci];
            tre += (wre*ur3 - wim*ui3) * cv;
            tim += (wre*ui3 + wim*ur3) * cv;
        }
      }
    double v = tre + tim;
    if (v < 1e-12 && v > -1e-12) return 0.0f;
    return (float)v;
}

// ---- compile-time schedule ----
constexpr int SEG_MAX = 256, RUN_MAX = 1024, ENT_MAX = 2048;
struct RoleTab {
    int nseg, nrun, nent;
    int seg_c[SEG_MAX]; int seg_s[SEG_MAX]; int seg_path[SEG_MAX];
    int seg_run_off[SEG_MAX + 1];
    int run_a[RUN_MAX];
    int run_ent_off[RUN_MAX + 1];
    int ent_b[ENT_MAX];
    float ent_cg[ENT_MAX];
};
struct Tab { RoleTab r[4]; };

constexpr Tab build_tab() {
    Tab T{};
    int pl1[NPATH]{}, pl2[NPATH]{}, pl3[NPATH]{};
    int np = 0;
    for (int l1 = 0; l1 <= 4; l1++)
      for (int l2 = 0; l2 <= 4; l2++) {
        int lo = l1 > l2 ? l1 - l2 : l2 - l1;
        int hi = (l1 + l2 > 4) ? 4 : (l1 + l2);
        for (int l3 = lo; l3 <= hi; l3++) { pl1[np]=l1; pl2[np]=l2; pl3[np]=l3; np++; }
      }
    int wsum[NLM]{};
    for (int p = 0; p < np; p++) {
        int l1 = pl1[p], l2 = pl2[p], l3 = pl3[p];
        int est = ((2*l1+1)*(2*l2+1) + 1) / 2 + 8;
        for (int c = l3*l3; c < (l3+1)*(l3+1); c++) wsum[c] += est;
    }
    int csel[NLM]{}; bool used[NLM]{}; int load[4]{};
    for (int it = 0; it < NLM; it++) {
        int best = -1, bw = -1;
        for (int c = 0; c < NLM; c++)
            if (!used[c] && wsum[c] > bw) { bw = wsum[c]; best = c; }
        int km = 0;
        for (int k2 = 1; k2 < 4; k2++) if (load[k2] < load[km]) km = k2;
        csel[best] = km; load[km] += bw; used[best] = true;
    }
    for (int r = 0; r < 4; r++) {
        RoleTab& R = T.r[r];
        R.seg_run_off[0] = 0; R.run_ent_off[0] = 0;
        for (int c = 0; c < NLM; c++) {
            if (csel[c] != r) continue;
            int l3c = cdeg_ct(c);
            for (int p = 0; p < np; p++) {
                if (pl3[p] != l3c) continue;
                int l1 = pl1[p], l2 = pl2[p];
                int srun = R.nrun;
                for (int a = l1*l1; a < (l1+1)*(l1+1); a++) {
                    int estart = R.nent;
                    for (int b = l2*l2; b < (l2+1)*(l2+1); b++) {
                        float v = realCG(a, b, c);
                        if (v != 0.0f) { R.ent_b[R.nent] = b; R.ent_cg[R.nent] = v; R.nent++; }
                    }
                    if (R.nent > estart) {
                        R.run_a[R.nrun] = a; R.nrun++; R.run_ent_off[R.nrun] = R.nent;
                    }
                }
                if (R.nrun > srun) {
                    R.seg_c[R.nseg] = c;
                    R.seg_s[R.nseg] = (l1 + l2 + l3c) & 1;
                    R.seg_path[R.nseg] = p;
                    R.nseg++; R.seg_run_off[R.nseg] = R.nrun;
                }
            }
        }
    }
    return T;
}
constexpr Tab TAB = build_tab();

// ================= template-generated TP products (scalar, CG as immediates) =================
// --- tp0 ---
template<int R, int E, int EEND> struct Ent0T {
    static __device__ __forceinline__ void go(float2 va, const char* sbb, float2& t) {
        constexpr int boff = TAB.r[R].ent_b[E] * 256;
        constexpr float cg = TAB.r[R].ent_cg[E];
        float2 vb = *(const float2*)(sbb + boff);
        t.x = fmaf(va.x * cg, vb.x, t.x);      // FMUL-imm + FFMA: constant in encoding
        t.y = fmaf(va.y * cg, vb.y, t.y);
        Ent0T<R, E + 1, EEND>::go(va, sbb, t);
    }
};
template<int R, int E> struct Ent0T<R, E, E> {
    static __device__ __forceinline__ void go(float2, const char*, float2&) {}
};

template<int R, int RI, int REND> struct Run0T {
    static __device__ __forceinline__ void go(const char* sab, const char* sbb, float2& t) {
        constexpr int aoff = TAB.r[R].run_a[RI] * 256;
        constexpr int e0 = TAB.r[R].run_ent_off[RI];
        constexpr int e1 = TAB.r[R].run_ent_off[RI + 1];
        float2 va = *(const float2*)(sab + aoff);
        Ent0T<R, e0, e1>::go(va, sbb, t);
        Run0T<R, RI + 1, REND>::go(sab, sbb, t);
    }
};
template<int R, int RI> struct Run0T<R, RI, RI> {
    static __device__ __forceinline__ void go(const char*, const char*, float2&) {}
};

template<int R, int SI, int SEND> struct Seg0T {
    static __device__ __forceinline__ void go(const char* sab, const char* sbb,
            const float* wq, float* yo, float2& acc0, float2& acc1) {
        constexpr int c = TAB.r[R].seg_c[SI];
        constexpr int s = TAB.r[R].seg_s[SI];
        constexpr int p = TAB.r[R].seg_path[SI];
        constexpr int r0 = TAB.r[R].seg_run_off[SI];
        constexpr int r1 = TAB.r[R].seg_run_off[SI + 1];
        float2 t = make_float2(0.f, 0.f);
        Run0T<R, r0, r1>::go(sab, sbb, t);
        float2 W00 = *(const float2*)(wq + p * 256);
        if (s == 0) {
            acc0.x = fmaf(W00.x, t.x, acc0.x);
            acc0.y = fmaf(W00.y, t.y, acc0.y);
        } else {
            acc1.x = fmaf(W00.x, t.x, acc1.x);
            acc1.y = fmaf(W00.y, t.y, acc1.y);
        }
        constexpr bool flush = (SI + 1 == SEND) || (TAB.r[R].seg_c[SI + 1] != c);
        if (flush) {
            *(float2*)(yo + c * 64) = acc0;
            *(float2*)(yo + (NLM + c) * 64) = acc1;
            acc0 = make_float2(0.f, 0.f);
            acc1 = make_float2(0.f, 0.f);
        }
        Seg0T<R, SI + 1, SEND>::go(sab, sbb, wq, yo, acc0, acc1);
    }
};
template<int R, int SI> struct Seg0T<R, SI, SI> {
    static __device__ __forceinline__ void go(const char*, const char*,
            const float*, float*, float2&, float2&) {}
};

// --- tp1 ---
template<int R, int E, int EEND> struct Ent1T {
    static __device__ __forceinline__ void go(float2 a0, float2 a1, const char* sbb,
            float2& t00, float2& t01, float2& t10, float2& t11) {
        constexpr int boff = TAB.r[R].ent_b[E] * 512;
        constexpr float cg = TAB.r[R].ent_cg[E];
        float2 b0 = *(const float2*)(sbb + boff);
        float2 b1 = *(const float2*)(sbb + boff + 256);
        float ca0x = a0.x * cg, ca0y = a0.y * cg;      // FMUL-imm
        float ca1x = a1.x * cg, ca1y = a1.y * cg;
        t00.x = fmaf(ca0x, b0.x, t00.x); t00.y = fmaf(ca0y, b0.y, t00.y);
        t01.x = fmaf(ca0x, b1.x, t01.x); t01.y = fmaf(ca0y, b1.y, t01.y);
        t10.x = fmaf(ca1x, b0.x, t10.x); t10.y = fmaf(ca1y, b0.y, t10.y);
        t11.x = fmaf(ca1x, b1.x, t11.x); t11.y = fmaf(ca1y, b1.y, t11.y);
        Ent1T<R, E + 1, EEND>::go(a0, a1, sbb, t00, t01, t10, t11);
    }
};
template<int R, int E> struct Ent1T<R, E, E> {
    static __device__ __forceinline__ void go(float2, float2, const char*,
            float2&, float2&, float2&, float2&) {}
};

template<int R, int RI, int REND> struct Run1T {
    static __device__ __forceinline__ void go(const char* sab, const char* sbb,
            float2& t00, float2& t01, float2& t10, float2& t11) {
        constexpr int aoff = TAB.r[R].run_a[RI] * 512;
        constexpr int e0 = TAB.r[R].run_ent_off[RI];
        constexpr int e1 = TAB.r[R].run_ent_off[RI + 1];
        float2 a0 = *(const float2*)(sab + aoff);
        float2 a1 = *(const float2*)(sab + aoff + 256);
        Ent1T<R, e0, e1>::go(a0, a1, sbb, t00, t01, t10, t11);
        Run1T<R, RI + 1, REND>::go(sab, sbb, t00, t01, t10, t11);
    }
};
template<int R, int RI> struct Run1T<R, RI, RI> {
    static __device__ __forceinline__ void go(const char*, const char*,
            float2&, float2&, float2&, float2&) {}
};

template<int R, int SI, int SEND> struct Seg1T {
    static __device__ __forceinline__ void go(const char* sab, const char* sbb,
            const float* wq, float* yo, float2& acc0, float2& acc1) {
        constexpr int c = TAB.r[R].seg_c[SI];
        constexpr int s = TAB.r[R].seg_s[SI];
        constexpr int p = TAB.r[R].seg_path[SI];
        constexpr int r0 = TAB.r[R].seg_run_off[SI];
        constexpr int r1 = TAB.r[R].seg_run_off[SI + 1];
        float2 t00 = make_float2(0.f, 0.f), t01 = make_float2(0.f, 0.f);
        float2 t10 = make_float2(0.f, 0.f), t11 = make_float2(0.f, 0.f);
        Run1T<R, r0, r1>::go(sab, sbb, t00, t01, t10, t11);
        const float* wpb = wq + p * 256;
        float2 W00 = *(const float2*)(wpb);
        float2 W01 = *(const float2*)(wpb + 64);
        float2 W10 = *(const float2*)(wpb + 128);
        float2 W11 = *(const float2*)(wpb + 192);
        float evx = fmaf(W11.x, t11.x, W00.x * t00.x);
        float evy = fmaf(W11.y, t11.y, W00.y * t00.y);
        float odx = fmaf(W10.x, t10.x, W01.x * t01.x);
        float ody = fmaf(W10.y, t10.y, W01.y * t01.y);
        if (s == 0) {
            acc0.x += evx; acc0.y += evy;
            acc1.x += odx; acc1.y += ody;
        } else {
            acc1.x += evx; acc1.y += evy;
            acc0.x += odx; acc0.y += ody;
        }
        constexpr bool flush = (SI + 1 == SEND) || (TAB.r[R].seg_c[SI + 1] != c);
        if (flush) {
            *(float2*)(yo + c * 64) = acc0;
            *(float2*)(yo + (NLM + c) * 64) = acc1;
            acc0 = make_float2(0.f, 0.f);
            acc1 = make_float2(0.f, 0.f);
        }
        Seg1T<R, SI + 1, SEND>::go(sab, sbb, wq, yo, acc0, acc1);
    }
};
template<int R, int SI> struct Seg1T<R, SI, SI> {
    static __device__ __forceinline__ void go(const char*, const char*,
            const float*, float*, float2&, float2&) {}
};

// ================= stage kernels =================
__global__ void k_zero(int total4) {
    int t = blockIdx.x * blockDim.x + threadIdx.x;
    if (t < total4) ((float4*)g_y0)[t] = make_float4(0.f, 0.f, 0.f, 0.f);
}

__global__ void k_edge(const int* __restrict__ nbr, const float* __restrict__ disp,
                       const int* __restrict__ Z, const float* __restrict__ Wsp,
                       const float* __restrict__ normp, int E) {
    int t = blockIdx.x * blockDim.x + threadIdx.x;
    int e = t >> 4, lane = t & 15;
    bool valid = (e < E);
    int i = 0, j = 0;
    float dx = 0.f, dy = 0.f, dz = 1.f;
    if (valid) {
        i = nbr[2 * e]; j = nbr[2 * e + 1];
        dx = disp[3 * e]; dy = disp[3 * e + 1]; dz = disp[3 * e + 2];
    }
    float r = sqrtf(dx * dx + dy * dy + dz * dz + 1e-12f);
    float inv = 1.0f / r;
    float x = dx * inv, y = dy * inv, z = dz * inv;
    bool ok = valid && (r < CUTOFF_F);
    float fcut = 0.5f * (cosf(PI_F * fminf(r * (1.0f / CUTOFF_F), 1.0f)) + 1.0f);

    int Zj = valid ? Z[j] : 0;
    const float gamma = 10.24f;
    float d = r - (float)lane * (CUTOFF_F / 15.0f);
    float rbf = expf(-gamma * d * d);

    const float* W = Wsp + Zj * 256 + lane;
    float gsum = 0.0f;
#pragma unroll
    for (int k = 0; k < 16; k++) {
        float rb = __shfl_sync(0xffffffffu, rbf, k, 16);
        gsum = fmaf(rb, W[k * 16], gsum);
    }
    if (!ok) return;
    float g = gsum * fcut / normp[0];

    float x2 = x * x, y2 = y * y, z2 = z * z;
    float Y[NLM];
    Y[0]  = 0.5f * sqrtf(1.0f / PI_F);
    Y[1]  = sqrtf(3.0f / (4.0f * PI_F)) * y;
    Y[2]  = sqrtf(3.0f / (4.0f * PI_F)) * z;
    Y[3]  = sqrtf(3.0f / (4.0f * PI_F)) * x;
    Y[4]  = 0.5f * sqrtf(15.0f / PI_F) * x * y;
    Y[5]  = 0.5f * sqrtf(15.0f / PI_F) * y * z;
    Y[6]  = 0.25f * sqrtf(5.0f / PI_F) * (3.0f * z2 - 1.0f);
    Y[7]  = 0.5f * sqrtf(15.0f / PI_F) * x * z;
    Y[8]  = 0.25f * sqrtf(15.0f / PI_F) * (x2 - y2);
    Y[9]  = 0.25f * sqrtf(35.0f / (2.0f * PI_F)) * y * (3.0f * x2 - y2);
    Y[10] = 0.5f * sqrtf(105.0f / PI_F) * x * y * z;
    Y[11] = 0.25f * sqrtf(21.0f / (2.0f * PI_F)) * y * (5.0f * z2 - 1.0f);
    Y[12] = 0.25f * sqrtf(7.0f / PI_F) * z * (5.0f * z2 - 3.0f);
    Y[13] = 0.25f * sqrtf(21.0f / (2.0f * PI_F)) * x * (5.0f * z2 - 1.0f);
    Y[14] = 0.25f * sqrtf(105.0f / PI_F) * z * (x2 - y2);
    Y[15] = 0.25f * sqrtf(35.0f / (2.0f * PI_F)) * x * (x2 - 3.0f * y2);
    Y[16] = 0.75f * sqrtf(35.0f / PI_F) * x * y * (x2 - y2);
    Y[17] = 0.75f * sqrtf(35.0f / (2.0f * PI_F)) * y * z * (3.0f * x2 - y2);
    Y[18] = 0.75f * sqrtf(5.0f / PI_F) * x * y * (7.0f * z2 - 1.0f);
    Y[19] = 0.75f * sqrtf(5.0f / (2.0f * PI_F)) * y * z * (7.0f * z2 - 3.0f);
    Y[20] = (3.0f / 16.0f) * sqrtf(1.0f / PI_F) * (35.0f * z2 * z2 - 30.0f * z2 + 3.0f);
    Y[21] = 0.75f * sqrtf(5.0f / (2.0f * PI_F)) * x * z * (7.0f * z2 - 3.0f);
    Y[22] = (3.0f / 8.0f) * sqrtf(5.0f / PI_F) * (x2 - y2) * (7.0f * z2 - 1.0f);
    Y[23] = 0.75f * sqrtf(35.0f / (2.0f * PI_F)) * x * z * (x2 - 3.0f * y2);
    Y[24] = (3.0f / 16.0f) * sqrtf(35.0f / PI_F) * (x2 * x2 - 6.0f * x2 * y2 + y2 * y2);

    float* dst = g_y0 + (size_t)i * (NLM * 16) + lane;
#pragma unroll
    for (int lm = 0; lm < NLM; lm++)
        atomicAdd(dst + lm * 16, Y[lm] * g);
}

// ---- TP layer 0 ----
__global__ void __launch_bounds__(128, 6) k_tp0(const float* __restrict__ W1,
                                                const float* __restrict__ W2,
                                                const float* __restrict__ wp) {
    __shared__ __align__(16) float sa[NLM * 64];
    __shared__ __align__(16) float sb[NLM * 64];
    int n = blockIdx.x;
    int tid = threadIdx.x;
    int g = tid & 63;
    int drole = tid >> 6;

    const float* yin = g_y0 + (size_t)n * (NLM * 16);
    const float* Wm = drole ? W2 : W1;
    float* dst = drole ? sb : sa;

    for (int d = 0; d < 5; d++) {
        float w[16];
        const float* Wb = Wm + (d * 16) * 64 + g;
#pragma unroll
        for (int f = 0; f < 16; f++) w[f] = Wb[f * 64];
        for (int lm = d * d; lm < (d + 1) * (d + 1); lm++) {
            const float4* s4 = (const float4*)(yin + lm * 16);
            float a0 = 0.f, a1 = 0.f, a2 = 0.f, a3 = 0.f;
#pragma unroll
            for (int k = 0; k < 4; k++) {
                float4 v = s4[k];
                a0 = fmaf(v.x, w[4*k+0], a0);
                a1 = fmaf(v.y, w[4*k+1], a1);
                a2 = fmaf(v.z, w[4*k+2], a2);
                a3 = fmaf(v.w, w[4*k+3], a3);
            }
            dst[lm * 64 + g] = (a0 + a1) + (a2 + a3);
        }
    }
    __syncthreads();

    int q = tid & 31;
    int role = tid >> 5;
    const char* sab = (const char*)sa + 8 * q;
    const char* sbb = (const char*)sb + 8 * q;
    const float* wq = wp + 2 * q;
    float* yo = g_y1 + (size_t)n * (2 * NLM * 64) + 2 * q;
    float2 acc0 = make_float2(0.f, 0.f), acc1 = make_float2(0.f, 0.f);
    if (role == 0)      Seg0T<0, 0, TAB.r[0].nseg>::go(sab, sbb, wq, yo, acc0, acc1);
    else if (role == 1) Seg0T<1, 0, TAB.r[1].nseg>::go(sab, sbb, wq, yo, acc0, acc1);
    else if (role == 2) Seg0T<2, 0, TAB.r[2].nseg>::go(sab, sbb, wq, yo, acc0, acc1);
    else                Seg0T<3, 0, TAB.r[3].nseg>::go(sab, sbb, wq, yo, acc0, acc1);
}

// ---- TP layer 1 ----
__global__ void __launch_bounds__(128, 6) k_tp1(const float* __restrict__ W1,
                                                const float* __restrict__ W2,
                                                const float* __restrict__ wp) {
    __shared__ __align__(16) float sa[NLM * 128];   // [a][p*64 + f] parity-major
    __shared__ __align__(16) float sb[NLM * 128];
    int n = blockIdx.x;
    int tid = threadIdx.x;
    int g = tid & 63;
    int drole = tid >> 6;

    const float* yin = g_y1 + (size_t)n * (2 * NLM * 64);
    const float* Wm = drole ? W2 : W1;
    float* dst = drole ? sb : sa;

    for (int p = 0; p < 2; p++) {
#pragma unroll
        for (int d = 0; d < 5; d++) {
            const int nlm = 2 * d + 1, lm0 = d * d;
            float accA[9], accB[9];
#pragma unroll
            for (int i = 0; i < nlm; i++) { accA[i] = 0.f; accB[i] = 0.f; }
#pragma unroll
            for (int kk = 0; kk < 4; kk++) {
                float w[16];
                const float* Wb = Wm + ((p * 5 + d) * 64 + kk * 16) * 64 + g;
#pragma unroll
                for (int f = 0; f < 16; f++) w[f] = Wb[f * 64];
#pragma unroll
                for (int i = 0; i < nlm; i++) {
                    const float4* s4 = (const float4*)(yin + (p * NLM + lm0 + i) * 64 + kk * 16);
#pragma unroll
                    for (int k2 = 0; k2 < 4; k2++) {
                        float4 v = s4[k2];
                        accA[i] = fmaf(v.x, w[4*k2+0], accA[i]);
                        accB[i] = fmaf(v.y, w[4*k2+1], accB[i]);
                        accA[i] = fmaf(v.z, w[4*k2+2], accA[i]);
                        accB[i] = fmaf(v.w, w[4*k2+3], accB[i]);
                    }
                }
            }
#pragma unroll
            for (int i = 0; i < nlm; i++)
                dst[(lm0 + i) * 128 + p * 64 + g] = accA[i] + accB[i];
        }
    }
    __syncthreads();

    int q = tid & 31;
    int role = tid >> 5;
    const char* sab = (const char*)sa + 8 * q;
    const char* sbb = (const char*)sb + 8 * q;
    const float* wq = wp + 2 * q;
    float* yo = g_y2 + (size_t)n * (2 * NLM * 64) + 2 * q;
    float2 acc0 = make_float2(0.f, 0.f), acc1 = make_float2(0.f, 0.f);
    if (role == 0)      Seg1T<0, 0, TAB.r[0].nseg>::go(sab, sbb, wq, yo, acc0, acc1);
    else if (role == 1) Seg1T<1, 0, TAB.r[1].nseg>::go(sab, sbb, wq, yo, acc0, acc1);
    else if (role == 2) Seg1T<2, 0, TAB.r[2].nseg>::go(sab, sbb, wq, yo, acc0, acc1);
    else                Seg1T<3, 0, TAB.r[3].nseg>::go(sab, sbb, wq, yo, acc0, acc1);
}

// ---- final ----
__global__ void __launch_bounds__(160) k_final(const int* __restrict__ Z,
                                               const float* __restrict__ emb,
                                               const float* __restrict__ W_et,
                                               const float* __restrict__ b_et,
                                               const float* __restrict__ wf,
                                               float* __restrict__ outp) {
    __shared__ float s_emb[64];
    int n = blockIdx.x;
    int t = threadIdx.x;
    if (t < 64) s_emb[t] = emb[Z[n] * 64 + t];
    __syncthreads();
    if (t >= 144) return;

    float te = b_et[t];
#pragma unroll
    for (int d = 0; d < 64; d++) te = fmaf(s_emb[d], W_et[d * 144 + t], te);

    for (int p = 0; p < 2; p++) {
        for (int lm = 0; lm < NLM; lm++) {
            float yc;
            if (t < 16)
                yc = (p == 0) ? g_y0[(size_t)n * (NLM * 16) + lm * 16 + t] : 0.0f;
            else if (t < 80)
                yc = g_y1[((size_t)n * 2 + p) * (NLM * 64) + lm * 64 + (t - 16)];
            else
                yc = g_y2[((size_t)n * 2 + p) * (NLM * 64) + lm * 64 + (t - 80)];
            float v = te * yc * wf[(p * 5 + c_deg[lm]) * 144 + t];
            if (p == 0 && lm == 0) v += te;
            float e = expf(fminf(v, 40.0f));
            float u = 1.0f + e;
            float u2 = u * u;
            float o = v * (2.0f * u2) / (u2 + 1.0f);
            outp[(((size_t)n * 2 + p) * NLM + lm) * 144 + t] = o;
        }
    }
}

// ---------------- launch ----------------
extern "C" void kernel_launch(void* const* d_in, const int* in_sizes, int n_in,
                              void* d_out, int out_size) {
    const int*   Z    = (const int*)d_in[0];
    const int*   nbr  = (const int*)d_in[1];
    const float* disp = (const float*)d_in[2];
    const float* Wsp  = (const float*)d_in[3];
    const float* emb  = (const float*)d_in[4];
    const float* W_et = (const float*)d_in[5];
    const float* b_et = (const float*)d_in[6];
    const float* norm = (const float*)d_in[7];
    const float* t0W1 = (const float*)d_in[8];
    const float* t0W2 = (const float*)d_in[9];
    const float* t0wp = (const float*)d_in[10];
    const float* t1W1 = (const float*)d_in[11];
    const float* t1W2 = (const float*)d_in[12];
    const float* t1wp = (const float*)d_in[13];
    const float* wfus = (const float*)d_in[14];
    float* outp = (float*)d_out;

    int N = in_sizes[0];
    int E = in_sizes[1] / 2;

    int tot4 = (N * NLM * 16) / 4;
    k_zero<<<(tot4 + 255) / 256, 256>>>(tot4);                          // 1
    k_edge<<<(E * 16 + 255) / 256, 256>>>(nbr, disp, Z, Wsp, norm, E);  // 2
    k_tp0<<<N, 128>>>(t0W1, t0W2, t0wp);                                // 3
    k_tp1<<<N, 128>>>(t1W1, t1W2, t1wp);                                // 4  <- profiled slot
    k_final<<<N, 160>>>(Z, emb, W_et, b_et, wfus, outp);                // 5
}

// round 14
// speedup vs baseline: 1.6990x; 1.6990x over previous
#include <cuda_runtime.h>
#include <math.h>

#define NLM 25
#define NPATH 65
#define PI_F 3.14159265358979323846f
#define CUTOFF_F 5.0f
#define MAXN 10240

// ---------------- scratch ----------------
__device__ float g_y0[MAXN * NLM * 16];
__device__ float g_y1[MAXN * 2 * NLM * 64];
__device__ float g_y2[MAXN * 2 * NLM * 64];

__constant__ int c_deg[NLM] = {0,1,1,1,2,2,2,2,2,3,3,3,3,3,3,3,4,4,4,4,4,4,4,4,4};

// volatile shared load, [reg + compile-time-immediate] addressing:
// - volatile => ptxas keeps program order, bounding the live-register window
// - "n" immediate => no address ALU, offset lives in the LDS encoding
template<int IMM>
__device__ __forceinline__ float2 lds2v(unsigned base) {
    float2 v;
    asm volatile("ld.shared.v2.f32 {%0, %1}, [%2+%3];"
                 : "=f"(v.x), "=f"(v.y) : "r"(base), "n"(IMM));
    return v;
}

__device__ __forceinline__ unsigned smem_u32(const void* p) {
    return (unsigned)__cvta_generic_to_shared(p);
}

// ================= compile-time CG construction =================
constexpr double CFACT[16] = {1.0,1.0,2.0,6.0,24.0,120.0,720.0,5040.0,40320.0,
                              362880.0,3628800.0,39916800.0,479001600.0,
                              6227020800.0,87178291200.0,1307674368000.0};

constexpr double csqrt_ct(double x) {
    if (x <= 0.0) return 0.0;
    double g = 1.0, t = x;
    while (t > 4.0) { t *= 0.25; g *= 2.0; }
    while (t < 0.25) { t *= 4.0; g *= 0.5; }
    double y = g * (0.5 + 0.5 * t);
    for (int i = 0; i < 10; i++) y = 0.5 * (y + x / y);
    return y;
}

constexpr int cdeg_ct(int i) { return i < 1 ? 0 : i < 4 ? 1 : i < 9 ? 2 : i < 16 ? 3 : 4; }

constexpr double cg_complex_ct(int l1,int m1,int l2,int m2,int l3,int m3) {
    if (m1 + m2 != m3) return 0.0;
    int lo = l1 > l2 ? l1 - l2 : l2 - l1;
    if (l3 < lo || l3 > l1 + l2) return 0.0;
    double P = CFACT[l1+l2-l3] * CFACT[l1-l2+l3] * CFACT[-l1+l2+l3] / CFACT[l1+l2+l3+1]
             * CFACT[l1+m1] * CFACT[l1-m1] * CFACT[l2+m2] * CFACT[l2-m2]
             * CFACT[l3+m3] * CFACT[l3-m3];
    double sp = csqrt_ct(P);
    int kmin = 0;
    if (l2 - l3 - m1 > kmin) kmin = l2 - l3 - m1;
    if (l1 - l3 + m2 > kmin) kmin = l1 - l3 + m2;
    int kmax = l1 + l2 - l3;
    if (l1 - m1 < kmax) kmax = l1 - m1;
    if (l2 + m2 < kmax) kmax = l2 + m2;
    double s = 0.0;
    for (int k = kmin; k <= kmax; k++) {
        double D = CFACT[k] * CFACT[l1+l2-l3-k] * CFACT[l1-m1-k] * CFACT[l2+m2-k]
                 * CFACT[l3-l2+m1+k] * CFACT[l3-l1-m2+k];
        s += ((k & 1) ? -1.0 : 1.0) * sp / D;
    }
    return csqrt_ct(2.0 * l3 + 1.0) * s;
}

struct DArr { double v[NLM * NLM * NLM]; };
constexpr DArr build_cc() {
    DArr A{};
    for (int l1 = 0; l1 <= 4; l1++)
    for (int m1 = -l1; m1 <= l1; m1++)
    for (int l2 = 0; l2 <= 4; l2++)
    for (int m2 = -l2; m2 <= l2; m2++) {
        int lo = l1 > l2 ? l1 - l2 : l2 - l1;
        int hi = (l1 + l2 > 4) ? 4 : (l1 + l2);
        for (int l3 = lo; l3 <= hi; l3++) {
            int m3 = m1 + m2;
            if (m3 >= -l3 && m3 <= l3)
                A.v[((l1*l1+l1+m1)*NLM + (l2*l2+l2+m2))*NLM + (l3*l3+l3+m3)]
                    = cg_complex_ct(l1, m1, l2, m2, l3, m3);
        }
    }
    return A;
}
constexpr DArr CC = build_cc();

struct URct { int col[2]; double re[2], im[2]; int n; };
constexpr URct u_row_ct(int l, int m) {
    URct u{};
    int off = l * l + l;
    const double is2 = 0.7071067811865476;
    if (m == 0) { u.col[0] = off; u.re[0] = 1.0; u.im[0] = 0.0; u.n = 1; return u; }
    if (m > 0) {
        double sgn = (m & 1) ? -1.0 : 1.0;
        u.col[0] = off + m; u.re[0] = sgn * is2; u.im[0] = 0.0;
        u.col[1] = off - m; u.re[1] = is2;       u.im[1] = 0.0;
        u.n = 2; return u;
    }
    int mm = -m;
    double sgn = (mm & 1) ? -1.0 : 1.0;
    u.col[0] = off - mm; u.re[0] = 0.0; u.im[0] = is2;
    u.col[1] = off + mm; u.re[1] = 0.0; u.im[1] = -sgn * is2;
    u.n = 2;
    return u;
}

constexpr float realCG(int i, int j, int k) {
    int li = cdeg_ct(i), mi = i - li*li - li;
    int lj = cdeg_ct(j), mj = j - lj*lj - lj;
    int lk = cdeg_ct(k), mk = k - lk*lk - lk;
    URct ua = u_row_ct(li, mi), ub = u_row_ct(lj, mj), uc = u_row_ct(lk, mk);
    double tre = 0.0, tim = 0.0;
    for (int aa = 0; aa < ua.n; aa++)
      for (int bb = 0; bb < ub.n; bb++) {
        double wre = ua.re[aa]*ub.re[bb] - ua.im[aa]*ub.im[bb];
        double wim = ua.re[aa]*ub.im[bb] + ua.im[aa]*ub.re[bb];
        for (int ci = 0; ci < uc.n; ci++) {
            double cv = CC.v[(ua.col[aa]*NLM + ub.col[bb])*NLM + uc.col[ci]];
            if (cv == 0.0) continue;
            double ur3 = uc.re[ci], ui3 = -uc.im[ci];
            tre += (wre*ur3 - wim*ui3) * cv;
            tim += (wre*ui3 + wim*ur3) * cv;
        }
      }
    double v = tre + tim;
    if (v < 1e-12 && v > -1e-12) return 0.0f;
    return (float)v;
}

// ---- compile-time schedule ----
constexpr int SEG_MAX = 256, RUN_MAX = 1024, ENT_MAX = 2048;
struct RoleTab {
    int nseg, nrun, nent;
    int seg_c[SEG_MAX]; int seg_s[SEG_MAX]; int seg_path[SEG_MAX];
    int seg_run_off[SEG_MAX + 1];
    int run_a[RUN_MAX];
    int run_ent_off[RUN_MAX + 1];
    int ent_b[ENT_MAX];
    float ent_cg[ENT_MAX];
};
struct Tab { RoleTab r[4]; };

constexpr Tab build_tab() {
    Tab T{};
    int pl1[NPATH]{}, pl2[NPATH]{}, pl3[NPATH]{};
    int np = 0;
    for (int l1 = 0; l1 <= 4; l1++)
      for (int l2 = 0; l2 <= 4; l2++) {
        int lo = l1 > l2 ? l1 - l2 : l2 - l1;
        int hi = (l1 + l2 > 4) ? 4 : (l1 + l2);
        for (int l3 = lo; l3 <= hi; l3++) { pl1[np]=l1; pl2[np]=l2; pl3[np]=l3; np++; }
      }
    int wsum[NLM]{};
    for (int p = 0; p < np; p++) {
        int l1 = pl1[p], l2 = pl2[p], l3 = pl3[p];
        int est = ((2*l1+1)*(2*l2+1) + 1) / 2 + 8;
        for (int c = l3*l3; c < (l3+1)*(l3+1); c++) wsum[c] += est;
    }
    int csel[NLM]{}; bool used[NLM]{}; int load[4]{};
    for (int it = 0; it < NLM; it++) {
        int best = -1, bw = -1;
        for (int c = 0; c < NLM; c++)
            if (!used[c] && wsum[c] > bw) { bw = wsum[c]; best = c; }
        int km = 0;
        for (int k2 = 1; k2 < 4; k2++) if (load[k2] < load[km]) km = k2;
        csel[best] = km; load[km] += bw; used[best] = true;
    }
    for (int r = 0; r < 4; r++) {
        RoleTab& R = T.r[r];
        R.seg_run_off[0] = 0; R.run_ent_off[0] = 0;
        for (int c = 0; c < NLM; c++) {
            if (csel[c] != r) continue;
            int l3c = cdeg_ct(c);
            for (int p = 0; p < np; p++) {
                if (pl3[p] != l3c) continue;
                int l1 = pl1[p], l2 = pl2[p];
                int srun = R.nrun;
                for (int a = l1*l1; a < (l1+1)*(l1+1); a++) {
                    int estart = R.nent;
                    for (int b = l2*l2; b < (l2+1)*(l2+1); b++) {
                        float v = realCG(a, b, c);
                        if (v != 0.0f) { R.ent_b[R.nent] = b; R.ent_cg[R.nent] = v; R.nent++; }
                    }
                    if (R.nent > estart) {
                        R.run_a[R.nrun] = a; R.nrun++; R.run_ent_off[R.nrun] = R.nent;
                    }
                }
                if (R.nrun > srun) {
                    R.seg_c[R.nseg] = c;
                    R.seg_s[R.nseg] = (l1 + l2 + l3c) & 1;
                    R.seg_path[R.nseg] = p;
                    R.nseg++; R.seg_run_off[R.nseg] = R.nrun;
                }
            }
        }
    }
    return T;
}
constexpr Tab TAB = build_tab();

// ================= template-generated TP products =================
// (scalar math, CG as instruction immediates, volatile LDS with imm offsets)
// --- tp0 ---
template<int R, int E, int EEND> struct Ent0T {
    static __device__ __forceinline__ void go(float2 va, unsigned sbb, float2& t) {
        constexpr int boff = TAB.r[R].ent_b[E] * 256;
        constexpr float cg = TAB.r[R].ent_cg[E];
        float2 vb = lds2v<boff>(sbb);
        t.x = fmaf(va.x * cg, vb.x, t.x);
        t.y = fmaf(va.y * cg, vb.y, t.y);
        Ent0T<R, E + 1, EEND>::go(va, sbb, t);
    }
};
template<int R, int E> struct Ent0T<R, E, E> {
    static __device__ __forceinline__ void go(float2, unsigned, float2&) {}
};

template<int R, int RI, int REND> struct Run0T {
    static __device__ __forceinline__ void go(unsigned sab, unsigned sbb, float2& t) {
        constexpr int aoff = TAB.r[R].run_a[RI] * 256;
        constexpr int e0 = TAB.r[R].run_ent_off[RI];
        constexpr int e1 = TAB.r[R].run_ent_off[RI + 1];
        float2 va = lds2v<aoff>(sab);
        Ent0T<R, e0, e1>::go(va, sbb, t);
        Run0T<R, RI + 1, REND>::go(sab, sbb, t);
    }
};
template<int R, int RI> struct Run0T<R, RI, RI> {
    static __device__ __forceinline__ void go(unsigned, unsigned, float2&) {}
};

template<int R, int SI, int SEND> struct Seg0T {
    static __device__ __forceinline__ void go(unsigned sab, unsigned sbb,
            const float* wq, float* yo, float2& acc0, float2& acc1) {
        constexpr int c = TAB.r[R].seg_c[SI];
        constexpr int s = TAB.r[R].seg_s[SI];
        constexpr int p = TAB.r[R].seg_path[SI];
        constexpr int r0 = TAB.r[R].seg_run_off[SI];
        constexpr int r1 = TAB.r[R].seg_run_off[SI + 1];
        float2 t = make_float2(0.f, 0.f);
        Run0T<R, r0, r1>::go(sab, sbb, t);
        float2 W00 = *(const float2*)(wq + p * 256);
        if (s == 0) {
            acc0.x = fmaf(W00.x, t.x, acc0.x);
            acc0.y = fmaf(W00.y, t.y, acc0.y);
        } else {
            acc1.x = fmaf(W00.x, t.x, acc1.x);
            acc1.y = fmaf(W00.y, t.y, acc1.y);
        }
        constexpr bool flush = (SI + 1 == SEND) || (TAB.r[R].seg_c[SI + 1] != c);
        if (flush) {
            *(float2*)(yo + c * 64) = acc0;
            *(float2*)(yo + (NLM + c) * 64) = acc1;
            acc0 = make_float2(0.f, 0.f);
            acc1 = make_float2(0.f, 0.f);
        }
        Seg0T<R, SI + 1, SEND>::go(sab, sbb, wq, yo, acc0, acc1);
    }
};
template<int R, int SI> struct Seg0T<R, SI, SI> {
    static __device__ __forceinline__ void go(unsigned, unsigned,
            const float*, float*, float2&, float2&) {}
};

// --- tp1 ---
template<int R, int E, int EEND> struct Ent1T {
    static __device__ __forceinline__ void go(float2 a0, float2 a1, unsigned sbb,
            float2& t00, float2& t01, float2& t10, float2& t11) {
        constexpr int boff = TAB.r[R].ent_b[E] * 512;
        constexpr float cg = TAB.r[R].ent_cg[E];
        float2 b0 = lds2v<boff>(sbb);
        float2 b1 = lds2v<boff + 256>(sbb);
        float ca0x = a0.x * cg, ca0y = a0.y * cg;   // FMUL-imm: cg in encoding
        float ca1x = a1.x * cg, ca1y = a1.y * cg;
        t00.x = fmaf(ca0x, b0.x, t00.x); t00.y = fmaf(ca0y, b0.y, t00.y);
        t01.x = fmaf(ca0x, b1.x, t01.x); t01.y = fmaf(ca0y, b1.y, t01.y);
        t10.x = fmaf(ca1x, b0.x, t10.x); t10.y = fmaf(ca1y, b0.y, t10.y);
        t11.x = fmaf(ca1x, b1.x, t11.x); t11.y = fmaf(ca1y, b1.y, t11.y);
        Ent1T<R, E + 1, EEND>::go(a0, a1, sbb, t00, t01, t10, t11);
    }
};
template<int R, int E> struct Ent1T<R, E, E> {
    static __device__ __forceinline__ void go(float2, float2, unsigned,
            float2&, float2&, float2&, float2&) {}
};

template<int R, int RI, int REND> struct Run1T {
    static __device__ __forceinline__ void go(unsigned sab, unsigned sbb,
            float2& t00, float2& t01, float2& t10, float2& t11) {
        constexpr int aoff = TAB.r[R].run_a[RI] * 512;
        constexpr int e0 = TAB.r[R].run_ent_off[RI];
        constexpr int e1 = TAB.r[R].run_ent_off[RI + 1];
        float2 a0 = lds2v<aoff>(sab);
        float2 a1 = lds2v<aoff + 256>(sab);
        Ent1T<R, e0, e1>::go(a0, a1, sbb, t00, t01, t10, t11);
        Run1T<R, RI + 1, REND>::go(sab, sbb, t00, t01, t10, t11);
    }
};
template<int R, int RI> struct Run1T<R, RI, RI> {
    static __device__ __forceinline__ void go(unsigned, unsigned,
            float2&, float2&, float2&, float2&) {}
};

template<int R, int SI, int SEND> struct Seg1T {
    static __device__ __forceinline__ void go(unsigned sab, unsigned sbb,
            const float* wq, float* yo, float2& acc0, float2& acc1) {
        constexpr int c = TAB.r[R].seg_c[SI];
        constexpr int s = TAB.r[R].seg_s[SI];
        constexpr int p = TAB.r[R].seg_path[SI];
        constexpr int r0 = TAB.r[R].seg_run_off[SI];
        constexpr int r1 = TAB.r[R].seg_run_off[SI + 1];
        float2 t00 = make_float2(0.f, 0.f), t01 = make_float2(0.f, 0.f);
        float2 t10 = make_float2(0.f, 0.f), t11 = make_float2(0.f, 0.f);
        Run1T<R, r0, r1>::go(sab, sbb, t00, t01, t10, t11);
        const float* wpb = wq + p * 256;
        float2 W00 = *(const float2*)(wpb);
        float2 W01 = *(const float2*)(wpb + 64);
        float2 W10 = *(const float2*)(wpb + 128);
        float2 W11 = *(const float2*)(wpb + 192);
        float evx = fmaf(W11.x, t11.x, W00.x * t00.x);
        float evy = fmaf(W11.y, t11.y, W00.y * t00.y);
        float odx = fmaf(W10.x, t10.x, W01.x * t01.x);
        float ody = fmaf(W10.y, t10.y, W01.y * t01.y);
        if (s == 0) {
            acc0.x += evx; acc0.y += evy;
            acc1.x += odx; acc1.y += ody;
        } else {
            acc1.x += evx; acc1.y += evy;
            acc0.x += odx; acc0.y += ody;
        }
        constexpr bool flush = (SI + 1 == SEND) || (TAB.r[R].seg_c[SI + 1] != c);
        if (flush) {
            *(float2*)(yo + c * 64) = acc0;
            *(float2*)(yo + (NLM + c) * 64) = acc1;
            acc0 = make_float2(0.f, 0.f);
            acc1 = make_float2(0.f, 0.f);
        }
        Seg1T<R, SI + 1, SEND>::go(sab, sbb, wq, yo, acc0, acc1);
    }
};
template<int R, int SI> struct Seg1T<R, SI, SI> {
    static __device__ __forceinline__ void go(unsigned, unsigned,
            const float*, float*, float2&, float2&) {}
};

// ================= stage kernels =================
__global__ void k_zero(int total4) {
    int t = blockIdx.x * blockDim.x + threadIdx.x;
    if (t < total4) ((float4*)g_y0)[t] = make_float4(0.f, 0.f, 0.f, 0.f);
}

__global__ void k_edge(const int* __restrict__ nbr, const float* __restrict__ disp,
                       const int* __restrict__ Z, const float* __restrict__ Wsp,
                       const float* __restrict__ normp, int E) {
    int t = blockIdx.x * blockDim.x + threadIdx.x;
    int e = t >> 4, lane = t & 15;
    bool valid = (e < E);
    int i = 0, j = 0;
    float dx = 0.f, dy = 0.f, dz = 1.f;
    if (valid) {
        i = nbr[2 * e]; j = nbr[2 * e + 1];
        dx = disp[3 * e]; dy = disp[3 * e + 1]; dz = disp[3 * e + 2];
    }
    float r = sqrtf(dx * dx + dy * dy + dz * dz + 1e-12f);
    float inv = 1.0f / r;
    float x = dx * inv, y = dy * inv, z = dz * inv;
    bool ok = valid && (r < CUTOFF_F);
    float fcut = 0.5f * (cosf(PI_F * fminf(r * (1.0f / CUTOFF_F), 1.0f)) + 1.0f);

    int Zj = valid ? Z[j] : 0;
    const float gamma = 10.24f;
    float d = r - (float)lane * (CUTOFF_F / 15.0f);
    float rbf = expf(-gamma * d * d);

    const float* W = Wsp + Zj * 256 + lane;
    float gsum = 0.0f;
#pragma unroll
    for (int k = 0; k < 16; k++) {
        float rb = __shfl_sync(0xffffffffu, rbf, k, 16);
        gsum = fmaf(rb, W[k * 16], gsum);
    }
    if (!ok) return;
    float g = gsum * fcut / normp[0];

    float x2 = x * x, y2 = y * y, z2 = z * z;
    float Y[NLM];
    Y[0]  = 0.5f * sqrtf(1.0f / PI_F);
    Y[1]  = sqrtf(3.0f / (4.0f * PI_F)) * y;
    Y[2]  = sqrtf(3.0f / (4.0f * PI_F)) * z;
    Y[3]  = sqrtf(3.0f / (4.0f * PI_F)) * x;
    Y[4]  = 0.5f * sqrtf(15.0f / PI_F) * x * y;
    Y[5]  = 0.5f * sqrtf(15.0f / PI_F) * y * z;
    Y[6]  = 0.25f * sqrtf(5.0f / PI_F) * (3.0f * z2 - 1.0f);
    Y[7]  = 0.5f * sqrtf(15.0f / PI_F) * x * z;
    Y[8]  = 0.25f * sqrtf(15.0f / PI_F) * (x2 - y2);
    Y[9]  = 0.25f * sqrtf(35.0f / (2.0f * PI_F)) * y * (3.0f * x2 - y2);
    Y[10] = 0.5f * sqrtf(105.0f / PI_F) * x * y * z;
    Y[11] = 0.25f * sqrtf(21.0f / (2.0f * PI_F)) * y * (5.0f * z2 - 1.0f);
    Y[12] = 0.25f * sqrtf(7.0f / PI_F) * z * (5.0f * z2 - 3.0f);
    Y[13] = 0.25f * sqrtf(21.0f / (2.0f * PI_F)) * x * (5.0f * z2 - 1.0f);
    Y[14] = 0.25f * sqrtf(105.0f / PI_F) * z * (x2 - y2);
    Y[15] = 0.25f * sqrtf(35.0f / (2.0f * PI_F)) * x * (x2 - 3.0f * y2);
    Y[16] = 0.75f * sqrtf(35.0f / PI_F) * x * y * (x2 - y2);
    Y[17] = 0.75f * sqrtf(35.0f / (2.0f * PI_F)) * y * z * (3.0f * x2 - y2);
    Y[18] = 0.75f * sqrtf(5.0f / PI_F) * x * y * (7.0f * z2 - 1.0f);
    Y[19] = 0.75f * sqrtf(5.0f / (2.0f * PI_F)) * y * z * (7.0f * z2 - 3.0f);
    Y[20] = (3.0f / 16.0f) * sqrtf(1.0f / PI_F) * (35.0f * z2 * z2 - 30.0f * z2 + 3.0f);
    Y[21] = 0.75f * sqrtf(5.0f / (2.0f * PI_F)) * x * z * (7.0f * z2 - 3.0f);
    Y[22] = (3.0f / 8.0f) * sqrtf(5.0f / PI_F) * (x2 - y2) * (7.0f * z2 - 1.0f);
    Y[23] = 0.75f * sqrtf(35.0f / (2.0f * PI_F)) * x * z * (x2 - 3.0f * y2);
    Y[24] = (3.0f / 16.0f) * sqrtf(35.0f / PI_F) * (x2 * x2 - 6.0f * x2 * y2 + y2 * y2);

    float* dst = g_y0 + (size_t)i * (NLM * 16) + lane;
#pragma unroll
    for (int lm = 0; lm < NLM; lm++)
        atomicAdd(dst + lm * 16, Y[lm] * g);
}

// ---- TP layer 0 ----
__global__ void __launch_bounds__(128) k_tp0(const float* __restrict__ W1,
                                             const float* __restrict__ W2,
                                             const float* __restrict__ wp) {
    __shared__ __align__(16) float sa[NLM * 64];
    __shared__ __align__(16) float sb[NLM * 64];
    int n = blockIdx.x;
    int tid = threadIdx.x;
    int g = tid & 63;
    int drole = tid >> 6;

    const float* yin = g_y0 + (size_t)n * (NLM * 16);
    const float* Wm = drole ? W2 : W1;
    float* dst = drole ? sb : sa;

    for (int d = 0; d < 5; d++) {
        float w[16];
        const float* Wb = Wm + (d * 16) * 64 + g;
#pragma unroll
        for (int f = 0; f < 16; f++) w[f] = Wb[f * 64];
        for (int lm = d * d; lm < (d + 1) * (d + 1); lm++) {
            const float4* s4 = (const float4*)(yin + lm * 16);
            float a0 = 0.f, a1 = 0.f, a2 = 0.f, a3 = 0.f;
#pragma unroll
            for (int k = 0; k < 4; k++) {
                float4 v = s4[k];
                a0 = fmaf(v.x, w[4*k+0], a0);
                a1 = fmaf(v.y, w[4*k+1], a1);
                a2 = fmaf(v.z, w[4*k+2], a2);
                a3 = fmaf(v.w, w[4*k+3], a3);
            }
            dst[lm * 64 + g] = (a0 + a1) + (a2 + a3);
        }
    }
    __syncthreads();

    int q = tid & 31;
    int role = tid >> 5;
    unsigned sab = smem_u32(sa) + 8 * q;
    unsigned sbb = smem_u32(sb) + 8 * q;
    const float* wq = wp + 2 * q;
    float* yo = g_y1 + (size_t)n * (2 * NLM * 64) + 2 * q;
    float2 acc0 = make_float2(0.f, 0.f), acc1 = make_float2(0.f, 0.f);
    if (role == 0)      Seg0T<0, 0, TAB.r[0].nseg>::go(sab, sbb, wq, yo, acc0, acc1);
    else if (role == 1) Seg0T<1, 0, TAB.r[1].nseg>::go(sab, sbb, wq, yo, acc0, acc1);
    else if (role == 2) Seg0T<2, 0, TAB.r[2].nseg>::go(sab, sbb, wq, yo, acc0, acc1);
    else                Seg0T<3, 0, TAB.r[3].nseg>::go(sab, sbb, wq, yo, acc0, acc1);
}

// ---- TP layer 1 ----
__global__ void __launch_bounds__(128) k_tp1(const float* __restrict__ W1,
                                             const float* __restrict__ W2,
                                             const float* __restrict__ wp) {
    __shared__ __align__(16) float sa[NLM * 128];   // [a][p*64 + f] parity-major
    __shared__ __align__(16) float sb[NLM * 128];
    int n = blockIdx.x;
    int tid = threadIdx.x;
    int g = tid & 63;
    int drole = tid >> 6;

    const float* yin = g_y1 + (size_t)n * (2 * NLM * 64);
    const float* Wm = drole ? W2 : W1;
    float* dst = drole ? sb : sa;

    for (int p = 0; p < 2; p++) {
#pragma unroll
        for (int d = 0; d < 5; d++) {
            const int nlm = 2 * d + 1, lm0 = d * d;
            float accA[9], accB[9];
#pragma unroll
            for (int i = 0; i < nlm; i++) { accA[i] = 0.f; accB[i] = 0.f; }
#pragma unroll
            for (int kk = 0; kk < 4; kk++) {
                float w[16];
                const float* Wb = Wm + ((p * 5 + d) * 64 + kk * 16) * 64 + g;
#pragma unroll
                for (int f = 0; f < 16; f++) w[f] = Wb[f * 64];
#pragma unroll
                for (int i = 0; i < nlm; i++) {
                    const float4* s4 = (const float4*)(yin + (p * NLM + lm0 + i) * 64 + kk * 16);
#pragma unroll
                    for (int k2 = 0; k2 < 4; k2++) {
                        float4 v = s4[k2];
                        accA[i] = fmaf(v.x, w[4*k2+0], accA[i]);
                        accB[i] = fmaf(v.y, w[4*k2+1], accB[i]);
                        accA[i] = fmaf(v.z, w[4*k2+2], accA[i]);
                        accB[i] = fmaf(v.w, w[4*k2+3], accB[i]);
                    }
                }
            }
#pragma unroll
            for (int i = 0; i < nlm; i++)
                dst[(lm0 + i) * 128 + p * 64 + g] = accA[i] + accB[i];
        }
    }
    __syncthreads();

    int q = tid & 31;
    int role = tid >> 5;
    unsigned sab = smem_u32(sa) + 8 * q;
    unsigned sbb = smem_u32(sb) + 8 * q;
    const float* wq = wp + 2 * q;
    float* yo = g_y2 + (size_t)n * (2 * NLM * 64) + 2 * q;
    float2 acc0 = make_float2(0.f, 0.f), acc1 = make_float2(0.f, 0.f);
    if (role == 0)      Seg1T<0, 0, TAB.r[0].nseg>::go(sab, sbb, wq, yo, acc0, acc1);
    else if (role == 1) Seg1T<1, 0, TAB.r[1].nseg>::go(sab, sbb, wq, yo, acc0, acc1);
    else if (role == 2) Seg1T<2, 0, TAB.r[2].nseg>::go(sab, sbb, wq, yo, acc0, acc1);
    else                Seg1T<3, 0, TAB.r[3].nseg>::go(sab, sbb, wq, yo, acc0, acc1);
}

// ---- final ----
__global__ void __launch_bounds__(160) k_final(const int* __restrict__ Z,
                                               const float* __restrict__ emb,
                                               const float* __restrict__ W_et,
                                               const float* __restrict__ b_et,
                                               const float* __restrict__ wf,
                                               float* __restrict__ outp) {
    __shared__ float s_emb[64];
    int n = blockIdx.x;
    int t = threadIdx.x;
    if (t < 64) s_emb[t] = emb[Z[n] * 64 + t];
    __syncthreads();
    if (t >= 144) return;

    float te = b_et[t];
#pragma unroll
    for (int d = 0; d < 64; d++) te = fmaf(s_emb[d], W_et[d * 144 + t], te);

    for (int p = 0; p < 2; p++) {
        for (int lm = 0; lm < NLM; lm++) {
            float yc;
            if (t < 16)
                yc = (p == 0) ? g_y0[(size_t)n * (NLM * 16) + lm * 16 + t] : 0.0f;
            else if (t < 80)
                yc = g_y1[((size_t)n * 2 + p) * (NLM * 64) + lm * 64 + (t - 16)];
            else
                yc = g_y2[((size_t)n * 2 + p) * (NLM * 64) + lm * 64 + (t - 80)];
            float v = te * yc * wf[(p * 5 + c_deg[lm]) * 144 + t];
            if (p == 0 && lm == 0) v += te;
            float e = expf(fminf(v, 40.0f));
            float u = 1.0f + e;
            float u2 = u * u;
            float o = v * (2.0f * u2) / (u2 + 1.0f);
            outp[(((size_t)n * 2 + p) * NLM + lm) * 144 + t] = o;
        }
    }
}

// ---------------- launch ----------------
extern "C" void kernel_launch(void* const* d_in, const int* in_sizes, int n_in,
                              void* d_out, int out_size) {
    const int*   Z    = (const int*)d_in[0];
    const int*   nbr  = (const int*)d_in[1];
    const float* disp = (const float*)d_in[2];
    const float* Wsp  = (const float*)d_in[3];
    const float* emb  = (const float*)d_in[4];
    const float* W_et = (const float*)d_in[5];
    const float* b_et = (const float*)d_in[6];
    const float* norm = (const float*)d_in[7];
    const float* t0W1 = (const float*)d_in[8];
    const float* t0W2 = (const float*)d_in[9];
    const float* t0wp = (const float*)d_in[10];
    const float* t1W1 = (const float*)d_in[11];
    const float* t1W2 = (const float*)d_in[12];
    const float* t1wp = (const float*)d_in[13];
    const float* wfus = (const float*)d_in[14];
    float* outp = (float*)d_out;

    int N = in_sizes[0];
    int E = in_sizes[1] / 2;

    int tot4 = (N * NLM * 16) / 4;
    k_zero<<<(tot4 + 255) / 256, 256>>>(tot4);                          // 1
    k_edge<<<(E * 16 + 255) / 256, 256>>>(nbr, disp, Z, Wsp, norm, E);  // 2
    k_tp0<<<N, 128>>>(t0W1, t0W2, t0wp);                                // 3
    k_tp1<<<N, 128>>>(t1W1, t1W2, t1wp);                                // 4  <- profiled slot
    k_final<<<N, 160>>>(Z, emb, W_et, b_et, wfus, outp);                // 5
}

// round 15
// speedup vs baseline: 2.9778x; 1.7527x over previous
#include <cuda_runtime.h>
#include <math.h>

#define NLM 25
#define NPATH 65
#define PI_F 3.14159265358979323846f
#define CUTOFF_F 5.0f
#define MAXN 10240

typedef unsigned long long ull;

// ---------------- scratch ----------------
__device__ float g_y0[MAXN * NLM * 16];
__device__ float g_y1[MAXN * 2 * NLM * 64];
__device__ float g_y2[MAXN * 2 * NLM * 64];

__constant__ int c_deg[NLM] = {0,1,1,1,2,2,2,2,2,3,3,3,3,3,3,3,4,4,4,4,4,4,4,4,4};

// ---------------- packed f32x2 helpers ----------------
__device__ __forceinline__ ull pmul2(ull a, ull b) {
    ull d; asm("mul.rn.f32x2 %0, %1, %2;" : "=l"(d) : "l"(a), "l"(b)); return d;
}
__device__ __forceinline__ void pfma2(ull& t, ull a, ull b) {
    asm("fma.rn.f32x2 %0, %1, %2, %0;" : "+l"(t) : "l"(a), "l"(b));
}
__device__ __forceinline__ ull pfma3(ull a, ull b, ull c) {
    ull d; asm("fma.rn.f32x2 %0, %1, %2, %3;" : "=l"(d) : "l"(a), "l"(b), "l"(c)); return d;
}
__device__ __forceinline__ ull padd2(ull a, ull b) {
    ull d; asm("add.rn.f32x2 %0, %1, %2;" : "=l"(d) : "l"(a), "l"(b)); return d;
}
__device__ __forceinline__ ull bcast2(float v) {
    ull d; asm("mov.b64 %0, {%1, %1};" : "=l"(d) : "f"(v)); return d;
}
__device__ __forceinline__ float2 up2(ull v) {
    float2 r; asm("mov.b64 {%0, %1}, %2;" : "=f"(r.x), "=f"(r.y) : "l"(v)); return r;
}

// ================= compile-time CG construction =================
constexpr double CFACT[16] = {1.0,1.0,2.0,6.0,24.0,120.0,720.0,5040.0,40320.0,
                              362880.0,3628800.0,39916800.0,479001600.0,
                              6227020800.0,87178291200.0,1307674368000.0};

constexpr double csqrt_ct(double x) {
    if (x <= 0.0) return 0.0;
    double g = 1.0, t = x;
    while (t > 4.0) { t *= 0.25; g *= 2.0; }
    while (t < 0.25) { t *= 4.0; g *= 0.5; }
    double y = g * (0.5 + 0.5 * t);
    for (int i = 0; i < 10; i++) y = 0.5 * (y + x / y);
    return y;
}

constexpr int cdeg_ct(int i) { return i < 1 ? 0 : i < 4 ? 1 : i < 9 ? 2 : i < 16 ? 3 : 4; }

constexpr double cg_complex_ct(int l1,int m1,int l2,int m2,int l3,int m3) {
    if (m1 + m2 != m3) return 0.0;
    int lo = l1 > l2 ? l1 - l2 : l2 - l1;
    if (l3 < lo || l3 > l1 + l2) return 0.0;
    double P = CFACT[l1+l2-l3] * CFACT[l1-l2+l3] * CFACT[-l1+l2+l3] / CFACT[l1+l2+l3+1]
             * CFACT[l1+m1] * CFACT[l1-m1] * CFACT[l2+m2] * CFACT[l2-m2]
             * CFACT[l3+m3] * CFACT[l3-m3];
    double sp = csqrt_ct(P);
    int kmin = 0;
    if (l2 - l3 - m1 > kmin) kmin = l2 - l3 - m1;
    if (l1 - l3 + m2 > kmin) kmin = l1 - l3 + m2;
    int kmax = l1 + l2 - l3;
    if (l1 - m1 < kmax) kmax = l1 - m1;
    if (l2 + m2 < kmax) kmax = l2 + m2;
    double s = 0.0;
    for (int k = kmin; k <= kmax; k++) {
        double D = CFACT[k] * CFACT[l1+l2-l3-k] * CFACT[l1-m1-k] * CFACT[l2+m2-k]
                 * CFACT[l3-l2+m1+k] * CFACT[l3-l1-m2+k];
        s += ((k & 1) ? -1.0 : 1.0) * sp / D;
    }
    return csqrt_ct(2.0 * l3 + 1.0) * s;
}

struct DArr { double v[NLM * NLM * NLM]; };
constexpr DArr build_cc() {
    DArr A{};
    for (int l1 = 0; l1 <= 4; l1++)
    for (int m1 = -l1; m1 <= l1; m1++)
    for (int l2 = 0; l2 <= 4; l2++)
    for (int m2 = -l2; m2 <= l2; m2++) {
        int lo = l1 > l2 ? l1 - l2 : l2 - l1;
        int hi = (l1 + l2 > 4) ? 4 : (l1 + l2);
        for (int l3 = lo; l3 <= hi; l3++) {
            int m3 = m1 + m2;
            if (m3 >= -l3 && m3 <= l3)
                A.v[((l1*l1+l1+m1)*NLM + (l2*l2+l2+m2))*NLM + (l3*l3+l3+m3)]
                    = cg_complex_ct(l1, m1, l2, m2, l3, m3);
        }
    }
    return A;
}
constexpr DArr CC = build_cc();

struct URct { int col[2]; double re[2], im[2]; int n; };
constexpr URct u_row_ct(int l, int m) {
    URct u{};
    int off = l * l + l;
    const double is2 = 0.7071067811865476;
    if (m == 0) { u.col[0] = off; u.re[0] = 1.0; u.im[0] = 0.0; u.n = 1; return u; }
    if (m > 0) {
        double sgn = (m & 1) ? -1.0 : 1.0;
        u.col[0] = off + m; u.re[0] = sgn * is2; u.im[0] = 0.0;
        u.col[1] = off - m; u.re[1] = is2;       u.im[1] = 0.0;
        u.n = 2; return u;
    }
    int mm = -m;
    double sgn = (mm & 1) ? -1.0 : 1.0;
    u.col[0] = off - mm; u.re[0] = 0.0; u.im[0] = is2;
    u.col[1] = off + mm; u.re[1] = 0.0; u.im[1] = -sgn * is2;
    u.n = 2;
    return u;
}

constexpr float realCG(int i, int j, int k) {
    int li = cdeg_ct(i), mi = i - li*li - li;
    int lj = cdeg_ct(j), mj = j - lj*lj - lj;
    int lk = cdeg_ct(k), mk = k - lk*lk - lk;
    URct ua = u_row_ct(li, mi), ub = u_row_ct(lj, mj), uc = u_row_ct(lk, mk);
    double tre = 0.0, tim = 0.0;
    for (int aa = 0; aa < ua.n; aa++)
      for (int bb = 0; bb < ub.n; bb++) {
        double wre = ua.re[aa]*ub.re[bb] - ua.im[aa]*ub.im[bb];
        double wim = ua.re[aa]*ub.im[bb] + ua.im[aa]*ub.re[bb];
        for (int ci = 0; ci < uc.n; ci++) {
            double cv = CC.v[(ua.col[aa]*NLM + ub.col[bb])*NLM + uc.col[ci]];
            if (cv == 0.0) continue;
            double ur3 = uc.re[ci], ui3 = -uc.im[ci];
            tre += (wre*ur3 - wim*ui3) * cv;
            tim += (wre*ui3 + wim*ur3) * cv;
        }
      }
    double v = tre + tim;
    if (v < 1e-12 && v > -1e-12) return 0.0f;
    return (float)v;
}

// ---- compile-time schedule ----
constexpr int SEG_MAX = 256, RUN_MAX = 1024, ENT_MAX = 2048;
struct RoleTab {
    int nseg, nrun, nent, ncgrp;
    int seg_c[SEG_MAX]; int seg_s[SEG_MAX]; int seg_path[SEG_MAX];
    int seg_run_off[SEG_MAX + 1];
    int cgrp_off[SEG_MAX + 1];        // segment-index boundaries of same-c groups
    int run_a[RUN_MAX];
    int run_ent_off[RUN_MAX + 1];
    int ent_b[ENT_MAX];
    float ent_cg[ENT_MAX];
};
struct Tab { RoleTab r[4]; };

constexpr Tab build_tab() {
    Tab T{};
    int pl1[NPATH]{}, pl2[NPATH]{}, pl3[NPATH]{};
    int np = 0;
    for (int l1 = 0; l1 <= 4; l1++)
      for (int l2 = 0; l2 <= 4; l2++) {
        int lo = l1 > l2 ? l1 - l2 : l2 - l1;
        int hi = (l1 + l2 > 4) ? 4 : (l1 + l2);
        for (int l3 = lo; l3 <= hi; l3++) { pl1[np]=l1; pl2[np]=l2; pl3[np]=l3; np++; }
      }
    int wsum[NLM]{};
    for (int p = 0; p < np; p++) {
        int l1 = pl1[p], l2 = pl2[p], l3 = pl3[p];
        int est = ((2*l1+1)*(2*l2+1) + 1) / 2 + 8;
        for (int c = l3*l3; c < (l3+1)*(l3+1); c++) wsum[c] += est;
    }
    int csel[NLM]{}; bool used[NLM]{}; int load[4]{};
    for (int it = 0; it < NLM; it++) {
        int best = -1, bw = -1;
        for (int c = 0; c < NLM; c++)
            if (!used[c] && wsum[c] > bw) { bw = wsum[c]; best = c; }
        int km = 0;
        for (int k2 = 1; k2 < 4; k2++) if (load[k2] < load[km]) km = k2;
        csel[best] = km; load[km] += bw; used[best] = true;
    }
    for (int r = 0; r < 4; r++) {
        RoleTab& R = T.r[r];
        R.seg_run_off[0] = 0; R.run_ent_off[0] = 0;
        for (int c = 0; c < NLM; c++) {
            if (csel[c] != r) continue;
            int l3c = cdeg_ct(c);
            for (int p = 0; p < np; p++) {
                if (pl3[p] != l3c) continue;
                int l1 = pl1[p], l2 = pl2[p];
                int srun = R.nrun;
                for (int a = l1*l1; a < (l1+1)*(l1+1); a++) {
                    int estart = R.nent;
                    for (int b = l2*l2; b < (l2+1)*(l2+1); b++) {
                        float v = realCG(a, b, c);
                        if (v != 0.0f) { R.ent_b[R.nent] = b; R.ent_cg[R.nent] = v; R.nent++; }
                    }
                    if (R.nent > estart) {
                        R.run_a[R.nrun] = a; R.nrun++; R.run_ent_off[R.nrun] = R.nent;
                    }
                }
                if (R.nrun > srun) {
                    R.seg_c[R.nseg] = c;
                    R.seg_s[R.nseg] = (l1 + l2 + l3c) & 1;
                    R.seg_path[R.nseg] = p;
                    R.nseg++; R.seg_run_off[R.nseg] = R.nrun;
                }
            }
        }
        // same-c group boundaries (segments are emitted grouped by c)
        R.ncgrp = 0; R.cgrp_off[0] = 0;
        for (int si = 0; si < R.nseg; si++) {
            if (si + 1 == R.nseg || R.seg_c[si + 1] != R.seg_c[si]) {
                R.ncgrp++; R.cgrp_off[R.ncgrp] = si + 1;
            }
        }
    }
    return T;
}
constexpr Tab TAB = build_tab();

// ================= template-generated TP products (R11 math) =================
// --- tp0 ---
template<int R, int E, int EEND> struct Ent0T {
    static __device__ __forceinline__ void go(ull va, const char* sbb, ull& t) {
        constexpr int boff = TAB.r[R].ent_b[E] * 256;
        constexpr float cgf = TAB.r[R].ent_cg[E];
        ull vb = *(const ull*)(sbb + boff);
        pfma2(t, pmul2(bcast2(cgf), va), vb);
        Ent0T<R, E + 1, EEND>::go(va, sbb, t);
    }
};
template<int R, int E> struct Ent0T<R, E, E> {
    static __device__ __forceinline__ void go(ull, const char*, ull&) {}
};

template<int R, int RI, int REND> struct Run0T {
    static __device__ __forceinline__ void go(const char* sab, const char* sbb, ull& t) {
        constexpr int aoff = TAB.r[R].run_a[RI] * 256;
        constexpr int e0 = TAB.r[R].run_ent_off[RI];
        constexpr int e1 = TAB.r[R].run_ent_off[RI + 1];
        ull va = *(const ull*)(sab + aoff);
        Ent0T<R, e0, e1>::go(va, sbb, t);
        Run0T<R, RI + 1, REND>::go(sab, sbb, t);
    }
};
template<int R, int RI> struct Run0T<R, RI, RI> {
    static __device__ __forceinline__ void go(const char*, const char*, ull&) {}
};

template<int R, int SI, int SEND> struct Seg0T {
    static __device__ __forceinline__ void go(const char* sab, const char* sbb,
            const float* wq, ull& acc0, ull& acc1) {
        constexpr int s = TAB.r[R].seg_s[SI];
        constexpr int p = TAB.r[R].seg_path[SI];
        constexpr int r0 = TAB.r[R].seg_run_off[SI];
        constexpr int r1 = TAB.r[R].seg_run_off[SI + 1];
        ull t = 0;
        Run0T<R, r0, r1>::go(sab, sbb, t);
        ull W00 = *(const ull*)(wq + p * 256);
        if (s == 0) acc0 = pfma3(W00, t, acc0);
        else        acc1 = pfma3(W00, t, acc1);
        Seg0T<R, SI + 1, SEND>::go(sab, sbb, wq, acc0, acc1);
    }
};
template<int R, int SI> struct Seg0T<R, SI, SI> {
    static __device__ __forceinline__ void go(const char*, const char*,
            const float*, ull&, ull&) {}
};

// one __noinline__ function per output-c group: hard wall for ptxas register
// allocation / constant hoisting (R11-R14: monolithic stream -> 255 regs + spills)
template<int R, int GI, int GEND> struct Grp0T {
    static __device__ __noinline__ void body(const char* sab, const char* sbb,
            const float* wq, float* yo) {
        constexpr int s0 = TAB.r[R].cgrp_off[GI];
        constexpr int s1 = TAB.r[R].cgrp_off[GI + 1];
        constexpr int c = TAB.r[R].seg_c[s0];
        ull acc0 = 0, acc1 = 0;
        Seg0T<R, s0, s1>::go(sab, sbb, wq, acc0, acc1);
        *(float2*)(yo + c * 64) = up2(acc0);
        *(float2*)(yo + (NLM + c) * 64) = up2(acc1);
    }
    static __device__ __forceinline__ void go(const char* sab, const char* sbb,
            const float* wq, float* yo) {
        body(sab, sbb, wq, yo);
        Grp0T<R, GI + 1, GEND>::go(sab, sbb, wq, yo);
    }
};
template<int R, int GI> struct Grp0T<R, GI, GI> {
    static __device__ __forceinline__ void go(const char*, const char*,
            const float*, float*) {}
};

// --- tp1 ---
template<int R, int E, int EEND> struct Ent1T {
    static __device__ __forceinline__ void go(ull a0, ull a1, const char* sbb,
            ull& t00, ull& t01, ull& t10, ull& t11) {
        constexpr int boff = TAB.r[R].ent_b[E] * 512;
        constexpr float cgf = TAB.r[R].ent_cg[E];
        ull cgcg = bcast2(cgf);
        ull b0 = *(const ull*)(sbb + boff);
        ull b1 = *(const ull*)(sbb + boff + 256);
        ull c0 = pmul2(cgcg, a0), c1 = pmul2(cgcg, a1);
        pfma2(t00, c0, b0); pfma2(t01, c0, b1);
        pfma2(t10, c1, b0); pfma2(t11, c1, b1);
        Ent1T<R, E + 1, EEND>::go(a0, a1, sbb, t00, t01, t10, t11);
    }
};
template<int R, int E> struct Ent1T<R, E, E> {
    static __device__ __forceinline__ void go(ull, ull, const char*, ull&, ull&, ull&, ull&) {}
};

template<int R, int RI, int REND> struct Run1T {
    static __device__ __forceinline__ void go(const char* sab, const char* sbb,
            ull& t00, ull& t01, ull& t10, ull& t11) {
        constexpr int aoff = TAB.r[R].run_a[RI] * 512;
        constexpr int e0 = TAB.r[R].run_ent_off[RI];
        constexpr int e1 = TAB.r[R].run_ent_off[RI + 1];
        ull a0 = *(const ull*)(sab + aoff);
        ull a1 = *(const ull*)(sab + aoff + 256);
        Ent1T<R, e0, e1>::go(a0, a1, sbb, t00, t01, t10, t11);
        Run1T<R, RI + 1, REND>::go(sab, sbb, t00, t01, t10, t11);
    }
};
template<int R, int RI> struct Run1T<R, RI, RI> {
    static __device__ __forceinline__ void go(const char*, const char*, ull&, ull&, ull&, ull&) {}
};

template<int R, int SI, int SEND> struct Seg1T {
    static __device__ __forceinline__ void go(const char* sab, const char* sbb,
            const float* wq, ull& acc0, ull& acc1) {
        constexpr int s = TAB.r[R].seg_s[SI];
        constexpr int p = TAB.r[R].seg_path[SI];
        constexpr int r0 = TAB.r[R].seg_run_off[SI];
        constexpr int r1 = TAB.r[R].seg_run_off[SI + 1];
        ull t00 = 0, t01 = 0, t10 = 0, t11 = 0;
        Run1T<R, r0, r1>::go(sab, sbb, t00, t01, t10, t11);
        const float* wpb = wq + p * 256;
        ull W00 = *(const ull*)(wpb);
        ull W01 = *(const ull*)(wpb + 64);
        ull W10 = *(const ull*)(wpb + 128);
        ull W11 = *(const ull*)(wpb + 192);
        ull ev = pfma3(W11, t11, pmul2(W00, t00));
        ull od = pfma3(W10, t10, pmul2(W01, t01));
        if (s == 0) { acc0 = padd2(acc0, ev); acc1 = padd2(acc1, od); }
        else        { acc1 = padd2(acc1, ev); acc0 = padd2(acc0, od); }
        Seg1T<R, SI + 1, SEND>::go(sab, sbb, wq, acc0, acc1);
    }
};
template<int R, int SI> struct Seg1T<R, SI, SI> {
    static __device__ __forceinline__ void go(const char*, const char*,
            const float*, ull&, ull&) {}
};

template<int R, int GI, int GEND> struct Grp1T {
    static __device__ __noinline__ void body(const char* sab, const char* sbb,
            const float* wq, float* yo) {
        constexpr int s0 = TAB.r[R].cgrp_off[GI];
        constexpr int s1 = TAB.r[R].cgrp_off[GI + 1];
        constexpr int c = TAB.r[R].seg_c[s0];
        ull acc0 = 0, acc1 = 0;
        Seg1T<R, s0, s1>::go(sab, sbb, wq, acc0, acc1);
        *(float2*)(yo + c * 64) = up2(acc0);
        *(float2*)(yo + (NLM + c) * 64) = up2(acc1);
    }
    static __device__ __forceinline__ void go(const char* sab, const char* sbb,
            const float* wq, float* yo) {
        body(sab, sbb, wq, yo);
        Grp1T<R, GI + 1, GEND>::go(sab, sbb, wq, yo);
    }
};
template<int R, int GI> struct Grp1T<R, GI, GI> {
    static __device__ __forceinline__ void go(const char*, const char*,
            const float*, float*) {}
};

// ================= stage kernels =================
__global__ void k_zero(int total4) {
    int t = blockIdx.x * blockDim.x + threadIdx.x;
    if (t < total4) ((float4*)g_y0)[t] = make_float4(0.f, 0.f, 0.f, 0.f);
}

__global__ void k_edge(const int* __restrict__ nbr, const float* __restrict__ disp,
                       const int* __restrict__ Z, const float* __restrict__ Wsp,
                       const float* __restrict__ normp, int E) {
    int t = blockIdx.x * blockDim.x + threadIdx.x;
    int e = t >> 4, lane = t & 15;
    bool valid = (e < E);
    int i = 0, j = 0;
    float dx = 0.f, dy = 0.f, dz = 1.f;
    if (valid) {
        i = nbr[2 * e]; j = nbr[2 * e + 1];
        dx = disp[3 * e]; dy = disp[3 * e + 1]; dz = disp[3 * e + 2];
    }
    float r = sqrtf(dx * dx + dy * dy + dz * dz + 1e-12f);
    float inv = 1.0f / r;
    float x = dx * inv, y = dy * inv, z = dz * inv;
    bool ok = valid && (r < CUTOFF_F);
    float fcut = 0.5f * (cosf(PI_F * fminf(r * (1.0f / CUTOFF_F), 1.0f)) + 1.0f);

    int Zj = valid ? Z[j] : 0;
    const float gamma = 10.24f;
    float d = r - (float)lane * (CUTOFF_F / 15.0f);
    float rbf = expf(-gamma * d * d);

    const float* W = Wsp + Zj * 256 + lane;
    float gsum = 0.0f;
#pragma unroll
    for (int k = 0; k < 16; k++) {
        float rb = __shfl_sync(0xffffffffu, rbf, k, 16);
        gsum = fmaf(rb, W[k * 16], gsum);
    }
    if (!ok) return;
    float g = gsum * fcut / normp[0];

    float x2 = x * x, y2 = y * y, z2 = z * z;
    float Y[NLM];
    Y[0]  = 0.5f * sqrtf(1.0f / PI_F);
    Y[1]  = sqrtf(3.0f / (4.0f * PI_F)) * y;
    Y[2]  = sqrtf(3.0f / (4.0f * PI_F)) * z;
    Y[3]  = sqrtf(3.0f / (4.0f * PI_F)) * x;
    Y[4]  = 0.5f * sqrtf(15.0f / PI_F) * x * y;
    Y[5]  = 0.5f * sqrtf(15.0f / PI_F) * y * z;
    Y[6]  = 0.25f * sqrtf(5.0f / PI_F) * (3.0f * z2 - 1.0f);
    Y[7]  = 0.5f * sqrtf(15.0f / PI_F) * x * z;
    Y[8]  = 0.25f * sqrtf(15.0f / PI_F) * (x2 - y2);
    Y[9]  = 0.25f * sqrtf(35.0f / (2.0f * PI_F)) * y * (3.0f * x2 - y2);
    Y[10] = 0.5f * sqrtf(105.0f / PI_F) * x * y * z;
    Y[11] = 0.25f * sqrtf(21.0f / (2.0f * PI_F)) * y * (5.0f * z2 - 1.0f);
    Y[12] = 0.25f * sqrtf(7.0f / PI_F) * z * (5.0f * z2 - 3.0f);
    Y[13] = 0.25f * sqrtf(21.0f / (2.0f * PI_F)) * x * (5.0f * z2 - 1.0f);
    Y[14] = 0.25f * sqrtf(105.0f / PI_F) * z * (x2 - y2);
    Y[15] = 0.25f * sqrtf(35.0f / (2.0f * PI_F)) * x * (x2 - 3.0f * y2);
    Y[16] = 0.75f * sqrtf(35.0f / PI_F) * x * y * (x2 - y2);
    Y[17] = 0.75f * sqrtf(35.0f / (2.0f * PI_F)) * y * z * (3.0f * x2 - y2);
    Y[18] = 0.75f * sqrtf(5.0f / PI_F) * x * y * (7.0f * z2 - 1.0f);
    Y[19] = 0.75f * sqrtf(5.0f / (2.0f * PI_F)) * y * z * (7.0f * z2 - 3.0f);
    Y[20] = (3.0f / 16.0f) * sqrtf(1.0f / PI_F) * (35.0f * z2 * z2 - 30.0f * z2 + 3.0f);
    Y[21] = 0.75f * sqrtf(5.0f / (2.0f * PI_F)) * x * z * (7.0f * z2 - 3.0f);
    Y[22] = (3.0f / 8.0f) * sqrtf(5.0f / PI_F) * (x2 - y2) * (7.0f * z2 - 1.0f);
    Y[23] = 0.75f * sqrtf(35.0f / (2.0f * PI_F)) * x * z * (x2 - 3.0f * y2);
    Y[24] = (3.0f / 16.0f) * sqrtf(35.0f / PI_F) * (x2 * x2 - 6.0f * x2 * y2 + y2 * y2);

    float* dst = g_y0 + (size_t)i * (NLM * 16) + lane;
#pragma unroll
    for (int lm = 0; lm < NLM; lm++)
        atomicAdd(dst + lm * 16, Y[lm] * g);
}

// ---- TP layer 0 ----
__global__ void __launch_bounds__(128) k_tp0(const float* __restrict__ W1,
                                             const float* __restrict__ W2,
                                             const float* __restrict__ wp) {
    __shared__ __align__(16) float sa[NLM * 64];
    __shared__ __align__(16) float sb[NLM * 64];
    int n = blockIdx.x;
    int tid = threadIdx.x;
    int g = tid & 63;
    int drole = tid >> 6;

    const float* yin = g_y0 + (size_t)n * (NLM * 16);
    const float* Wm = drole ? W2 : W1;
    float* dst = drole ? sb : sa;

    for (int d = 0; d < 5; d++) {
        float w[16];
        const float* Wb = Wm + (d * 16) * 64 + g;
#pragma unroll
        for (int f = 0; f < 16; f++) w[f] = Wb[f * 64];
        for (int lm = d * d; lm < (d + 1) * (d + 1); lm++) {
            const float4* s4 = (const float4*)(yin + lm * 16);
            float a0 = 0.f, a1 = 0.f, a2 = 0.f, a3 = 0.f;
#pragma unroll
            for (int k = 0; k < 4; k++) {
                float4 v = s4[k];
                a0 = fmaf(v.x, w[4*k+0], a0);
                a1 = fmaf(v.y, w[4*k+1], a1);
                a2 = fmaf(v.z, w[4*k+2], a2);
                a3 = fmaf(v.w, w[4*k+3], a3);
            }
            dst[lm * 64 + g] = (a0 + a1) + (a2 + a3);
        }
    }
    __syncthreads();

    int q = tid & 31;
    int role = tid >> 5;
    const char* sab = (const char*)sa + 8 * q;
    const char* sbb = (const char*)sb + 8 * q;
    const float* wq = wp + 2 * q;
    float* yo = g_y1 + (size_t)n * (2 * NLM * 64) + 2 * q;
    if (role == 0)      Grp0T<0, 0, TAB.r[0].ncgrp>::go(sab, sbb, wq, yo);
    else if (role == 1) Grp0T<1, 0, TAB.r[1].ncgrp>::go(sab, sbb, wq, yo);
    else if (role == 2) Grp0T<2, 0, TAB.r[2].ncgrp>::go(sab, sbb, wq, yo);
    else                Grp0T<3, 0, TAB.r[3].ncgrp>::go(sab, sbb, wq, yo);
}

// ---- TP layer 1 ----
__global__ void __launch_bounds__(128) k_tp1(const float* __restrict__ W1,
                                             const float* __restrict__ W2,
                                             const float* __restrict__ wp) {
    __shared__ __align__(16) float sa[NLM * 128];   // [a][p*64 + f] parity-major
    __shared__ __align__(16) float sb[NLM * 128];
    int n = blockIdx.x;
    int tid = threadIdx.x;
    int g = tid & 63;
    int drole = tid >> 6;

    const float* yin = g_y1 + (size_t)n * (2 * NLM * 64);
    const float* Wm = drole ? W2 : W1;
    float* dst = drole ? sb : sa;

    for (int p = 0; p < 2; p++) {
#pragma unroll
        for (int d = 0; d < 5; d++) {
            const int nlm = 2 * d + 1, lm0 = d * d;
            float accA[9], accB[9];
#pragma unroll
            for (int i = 0; i < nlm; i++) { accA[i] = 0.f; accB[i] = 0.f; }
#pragma unroll
            for (int kk = 0; kk < 4; kk++) {
                float w[16];
                const float* Wb = Wm + ((p * 5 + d) * 64 + kk * 16) * 64 + g;
#pragma unroll
                for (int f = 0; f < 16; f++) w[f] = Wb[f * 64];
#pragma unroll
                for (int i = 0; i < nlm; i++) {
                    const float4* s4 = (const float4*)(yin + (p * NLM + lm0 + i) * 64 + kk * 16);
#pragma unroll
                    for (int k2 = 0; k2 < 4; k2++) {
                        float4 v = s4[k2];
                        accA[i] = fmaf(v.x, w[4*k2+0], accA[i]);
                        accB[i] = fmaf(v.y, w[4*k2+1], accB[i]);
                        accA[i] = fmaf(v.z, w[4*k2+2], accA[i]);
                        accB[i] = fmaf(v.w, w[4*k2+3], accB[i]);
                    }
                }
            }
#pragma unroll
            for (int i = 0; i < nlm; i++)
                dst[(lm0 + i) * 128 + p * 64 + g] = accA[i] + accB[i];
        }
    }
    __syncthreads();

    int q = tid & 31;
    int role = tid >> 5;
    const char* sab = (const char*)sa + 8 * q;
    const char* sbb = (const char*)sb + 8 * q;
    const float* wq = wp + 2 * q;
    float* yo = g_y2 + (size_t)n * (2 * NLM * 64) + 2 * q;
    if (role == 0)      Grp1T<0, 0, TAB.r[0].ncgrp>::go(sab, sbb, wq, yo);
    else if (role == 1) Grp1T<1, 0, TAB.r[1].ncgrp>::go(sab, sbb, wq, yo);
    else if (role == 2) Grp1T<2, 0, TAB.r[2].ncgrp>::go(sab, sbb, wq, yo);
    else                Grp1T<3, 0, TAB.r[3].ncgrp>::go(sab, sbb, wq, yo);
}

// ---- final ----
__global__ void __launch_bounds__(160) k_final(const int* __restrict__ Z,
                                               const float* __restrict__ emb,
                                               const float* __restrict__ W_et,
                                               const float* __restrict__ b_et,
                                               const float* __restrict__ wf,
                                               float* __restrict__ outp) {
    __shared__ float s_emb[64];
    int n = blockIdx.x;
    int t = threadIdx.x;
    if (t < 64) s_emb[t] = emb[Z[n] * 64 + t];
    __syncthreads();
    if (t >= 144) return;

    float te = b_et[t];
#pragma unroll
    for (int d = 0; d < 64; d++) te = fmaf(s_emb[d], W_et[d * 144 + t], te);

    for (int p = 0; p < 2; p++) {
        for (int lm = 0; lm < NLM; lm++) {
            float yc;
            if (t < 16)
                yc = (p == 0) ? g_y0[(size_t)n * (NLM * 16) + lm * 16 + t] : 0.0f;
            else if (t < 80)
                yc = g_y1[((size_t)n * 2 + p) * (NLM * 64) + lm * 64 + (t - 16)];
            else
                yc = g_y2[((size_t)n * 2 + p) * (NLM * 64) + lm * 64 + (t - 80)];
            float v = te * yc * wf[(p * 5 + c_deg[lm]) * 144 + t];
            if (p == 0 && lm == 0) v += te;
            float e = expf(fminf(v, 40.0f));
            float u = 1.0f + e;
            float u2 = u * u;
            float o = v * (2.0f * u2) / (u2 + 1.0f);
            outp[(((size_t)n * 2 + p) * NLM + lm) * 144 + t] = o;
        }
    }
}

// ---------------- launch ----------------
extern "C" void kernel_launch(void* const* d_in, const int* in_sizes, int n_in,
                              void* d_out, int out_size) {
    const int*   Z    = (const int*)d_in[0];
    const int*   nbr  = (const int*)d_in[1];
    const float* disp = (const float*)d_in[2];
    const float* Wsp  = (const float*)d_in[3];
    const float* emb  = (const float*)d_in[4];
    const float* W_et = (const float*)d_in[5];
    const float* b_et = (const float*)d_in[6];
    const float* norm = (const float*)d_in[7];
    const float* t0W1 = (const float*)d_in[8];
    const float* t0W2 = (const float*)d_in[9];
    const float* t0wp = (const float*)d_in[10];
    const float* t1W1 = (const float*)d_in[11];
    const float* t1W2 = (const float*)d_in[12];
    const float* t1wp = (const float*)d_in[13];
    const float* wfus = (const float*)d_in[14];
    float* outp = (float*)d_out;

    int N = in_sizes[0];
    int E = in_sizes[1] / 2;

    int tot4 = (N * NLM * 16) / 4;
    k_zero<<<(tot4 + 255) / 256, 256>>>(tot4);                          // 1
    k_edge<<<(E * 16 + 255) / 256, 256>>>(nbr, disp, Z, Wsp, norm, E);  // 2
    k_tp0<<<N, 128>>>(t0W1, t0W2, t0wp);                                // 3
    k_tp1<<<N, 128>>>(t1W1, t1W2, t1wp);                                // 4  <- profiled slot
    k_final<<<N, 160>>>(Z, emb, W_et, b_et, wfus, outp);                // 5
}

// round 16
// speedup vs baseline: 3.1628x; 1.0621x over previous
#include <cuda_runtime.h>
#include <math.h>

#define NLM 25
#define NPATH 65
#define PI_F 3.14159265358979323846f
#define CUTOFF_F 5.0f
#define MAXN 10240
#define GRP_CAP 24   // max CG entries per __noinline__ group body (register-pressure cap)

typedef unsigned long long ull;

// ---------------- scratch ----------------
__device__ float g_y0[MAXN * NLM * 16];
__device__ float g_y1[MAXN * 2 * NLM * 64];
__device__ float g_y2[MAXN * 2 * NLM * 64];

__constant__ int c_deg[NLM] = {0,1,1,1,2,2,2,2,2,3,3,3,3,3,3,3,4,4,4,4,4,4,4,4,4};

// ---------------- packed f32x2 helpers ----------------
__device__ __forceinline__ ull pmul2(ull a, ull b) {
    ull d; asm("mul.rn.f32x2 %0, %1, %2;" : "=l"(d) : "l"(a), "l"(b)); return d;
}
__device__ __forceinline__ void pfma2(ull& t, ull a, ull b) {
    asm("fma.rn.f32x2 %0, %1, %2, %0;" : "+l"(t) : "l"(a), "l"(b));
}
__device__ __forceinline__ ull pfma3(ull a, ull b, ull c) {
    ull d; asm("fma.rn.f32x2 %0, %1, %2, %3;" : "=l"(d) : "l"(a), "l"(b), "l"(c)); return d;
}
__device__ __forceinline__ ull padd2(ull a, ull b) {
    ull d; asm("add.rn.f32x2 %0, %1, %2;" : "=l"(d) : "l"(a), "l"(b)); return d;
}
__device__ __forceinline__ ull bcast2(float v) {
    ull d; asm("mov.b64 %0, {%1, %1};" : "=l"(d) : "f"(v)); return d;
}
__device__ __forceinline__ float2 up2(ull v) {
    float2 r; asm("mov.b64 {%0, %1}, %2;" : "=f"(r.x), "=f"(r.y) : "l"(v)); return r;
}

// ================= compile-time CG construction =================
constexpr double CFACT[16] = {1.0,1.0,2.0,6.0,24.0,120.0,720.0,5040.0,40320.0,
                              362880.0,3628800.0,39916800.0,479001600.0,
                              6227020800.0,87178291200.0,1307674368000.0};

constexpr double csqrt_ct(double x) {
    if (x <= 0.0) return 0.0;
    double g = 1.0, t = x;
    while (t > 4.0) { t *= 0.25; g *= 2.0; }
    while (t < 0.25) { t *= 4.0; g *= 0.5; }
    double y = g * (0.5 + 0.5 * t);
    for (int i = 0; i < 10; i++) y = 0.5 * (y + x / y);
    return y;
}

constexpr int cdeg_ct(int i) { return i < 1 ? 0 : i < 4 ? 1 : i < 9 ? 2 : i < 16 ? 3 : 4; }

constexpr double cg_complex_ct(int l1,int m1,int l2,int m2,int l3,int m3) {
    if (m1 + m2 != m3) return 0.0;
    int lo = l1 > l2 ? l1 - l2 : l2 - l1;
    if (l3 < lo || l3 > l1 + l2) return 0.0;
    double P = CFACT[l1+l2-l3] * CFACT[l1-l2+l3] * CFACT[-l1+l2+l3] / CFACT[l1+l2+l3+1]
             * CFACT[l1+m1] * CFACT[l1-m1] * CFACT[l2+m2] * CFACT[l2-m2]
             * CFACT[l3+m3] * CFACT[l3-m3];
    double sp = csqrt_ct(P);
    int kmin = 0;
    if (l2 - l3 - m1 > kmin) kmin = l2 - l3 - m1;
    if (l1 - l3 + m2 > kmin) kmin = l1 - l3 + m2;
    int kmax = l1 + l2 - l3;
    if (l1 - m1 < kmax) kmax = l1 - m1;
    if (l2 + m2 < kmax) kmax = l2 + m2;
    double s = 0.0;
    for (int k = kmin; k <= kmax; k++) {
        double D = CFACT[k] * CFACT[l1+l2-l3-k] * CFACT[l1-m1-k] * CFACT[l2+m2-k]
                 * CFACT[l3-l2+m1+k] * CFACT[l3-l1-m2+k];
        s += ((k & 1) ? -1.0 : 1.0) * sp / D;
    }
    return csqrt_ct(2.0 * l3 + 1.0) * s;
}

struct DArr { double v[NLM * NLM * NLM]; };
constexpr DArr build_cc() {
    DArr A{};
    for (int l1 = 0; l1 <= 4; l1++)
    for (int m1 = -l1; m1 <= l1; m1++)
    for (int l2 = 0; l2 <= 4; l2++)
    for (int m2 = -l2; m2 <= l2; m2++) {
        int lo = l1 > l2 ? l1 - l2 : l2 - l1;
        int hi = (l1 + l2 > 4) ? 4 : (l1 + l2);
        for (int l3 = lo; l3 <= hi; l3++) {
            int m3 = m1 + m2;
            if (m3 >= -l3 && m3 <= l3)
                A.v[((l1*l1+l1+m1)*NLM + (l2*l2+l2+m2))*NLM + (l3*l3+l3+m3)]
                    = cg_complex_ct(l1, m1, l2, m2, l3, m3);
        }
    }
    return A;
}
constexpr DArr CC = build_cc();

struct URct { int col[2]; double re[2], im[2]; int n; };
constexpr URct u_row_ct(int l, int m) {
    URct u{};
    int off = l * l + l;
    const double is2 = 0.7071067811865476;
    if (m == 0) { u.col[0] = off; u.re[0] = 1.0; u.im[0] = 0.0; u.n = 1; return u; }
    if (m > 0) {
        double sgn = (m & 1) ? -1.0 : 1.0;
        u.col[0] = off + m; u.re[0] = sgn * is2; u.im[0] = 0.0;
        u.col[1] = off - m; u.re[1] = is2;       u.im[1] = 0.0;
        u.n = 2; return u;
    }
    int mm = -m;
    double sgn = (mm & 1) ? -1.0 : 1.0;
    u.col[0] = off - mm; u.re[0] = 0.0; u.im[0] = is2;
    u.col[1] = off + mm; u.re[1] = 0.0; u.im[1] = -sgn * is2;
    u.n = 2;
    return u;
}

constexpr float realCG(int i, int j, int k) {
    int li = cdeg_ct(i), mi = i - li*li - li;
    int lj = cdeg_ct(j), mj = j - lj*lj - lj;
    int lk = cdeg_ct(k), mk = k - lk*lk - lk;
    URct ua = u_row_ct(li, mi), ub = u_row_ct(lj, mj), uc = u_row_ct(lk, mk);
    double tre = 0.0, tim = 0.0;
    for (int aa = 0; aa < ua.n; aa++)
      for (int bb = 0; bb < ub.n; bb++) {
        double wre = ua.re[aa]*ub.re[bb] - ua.im[aa]*ub.im[bb];
        double wim = ua.re[aa]*ub.im[bb] + ua.im[aa]*ub.re[bb];
        for (int ci = 0; ci < uc.n; ci++) {
            double cv = CC.v[(ua.col[aa]*NLM + ub.col[bb])*NLM + uc.col[ci]];
            if (cv == 0.0) continue;
            double ur3 = uc.re[ci], ui3 = -uc.im[ci];
            tre += (wre*ur3 - wim*ui3) * cv;
            tim += (wre*ui3 + wim*ur3) * cv;
        }
      }
    double v = tre + tim;
    if (v < 1e-12 && v > -1e-12) return 0.0f;
    return (float)v;
}

// ---- compile-time schedule ----
constexpr int SEG_MAX = 256, RUN_MAX = 1024, ENT_MAX = 2048;
struct RoleTab {
    int nseg, nrun, nent, ncgrp;
    int seg_c[SEG_MAX]; int seg_s[SEG_MAX]; int seg_path[SEG_MAX];
    int seg_run_off[SEG_MAX + 1];
    int cgrp_off[SEG_MAX + 1];    // segment-index boundaries of groups
    int grp_first[SEG_MAX];       // 1 if this group starts a new output c
    int run_a[RUN_MAX];
    int run_ent_off[RUN_MAX + 1];
    int ent_b[ENT_MAX];
    float ent_cg[ENT_MAX];
};
struct Tab { RoleTab r[4]; };

constexpr Tab build_tab() {
    Tab T{};
    int pl1[NPATH]{}, pl2[NPATH]{}, pl3[NPATH]{};
    int np = 0;
    for (int l1 = 0; l1 <= 4; l1++)
      for (int l2 = 0; l2 <= 4; l2++) {
        int lo = l1 > l2 ? l1 - l2 : l2 - l1;
        int hi = (l1 + l2 > 4) ? 4 : (l1 + l2);
        for (int l3 = lo; l3 <= hi; l3++) { pl1[np]=l1; pl2[np]=l2; pl3[np]=l3; np++; }
      }
    int wsum[NLM]{};
    for (int p = 0; p < np; p++) {
        int l1 = pl1[p], l2 = pl2[p], l3 = pl3[p];
        int est = ((2*l1+1)*(2*l2+1) + 1) / 2 + 8;
        for (int c = l3*l3; c < (l3+1)*(l3+1); c++) wsum[c] += est;
    }
    int csel[NLM]{}; bool used[NLM]{}; int load[4]{};
    for (int it = 0; it < NLM; it++) {
        int best = -1, bw = -1;
        for (int c = 0; c < NLM; c++)
            if (!used[c] && wsum[c] > bw) { bw = wsum[c]; best = c; }
        int km = 0;
        for (int k2 = 1; k2 < 4; k2++) if (load[k2] < load[km]) km = k2;
        csel[best] = km; load[km] += bw; used[best] = true;
    }
    for (int r = 0; r < 4; r++) {
        RoleTab& R = T.r[r];
        R.seg_run_off[0] = 0; R.run_ent_off[0] = 0;
        for (int c = 0; c < NLM; c++) {
            if (csel[c] != r) continue;
            int l3c = cdeg_ct(c);
            for (int p = 0; p < np; p++) {
                if (pl3[p] != l3c) continue;
                int l1 = pl1[p], l2 = pl2[p];
                int srun = R.nrun;
                for (int a = l1*l1; a < (l1+1)*(l1+1); a++) {
                    int estart = R.nent;
                    for (int b = l2*l2; b < (l2+1)*(l2+1); b++) {
                        float v = realCG(a, b, c);
                        if (v != 0.0f) { R.ent_b[R.nent] = b; R.ent_cg[R.nent] = v; R.nent++; }
                    }
                    if (R.nent > estart) {
                        R.run_a[R.nrun] = a; R.nrun++; R.run_ent_off[R.nrun] = R.nent;
                    }
                }
                if (R.nrun > srun) {
                    R.seg_c[R.nseg] = c;
                    R.seg_s[R.nseg] = (l1 + l2 + l3c) & 1;
                    R.seg_path[R.nseg] = p;
                    R.nseg++; R.seg_run_off[R.nseg] = R.nrun;
                }
            }
        }
        // group boundaries: close on c-change OR entry-count cap
        R.ncgrp = 0; R.cgrp_off[0] = 0;
        int entcnt = 0;
        for (int si = 0; si < R.nseg; si++) {
            int se = R.run_ent_off[R.seg_run_off[si + 1]]
                   - R.run_ent_off[R.seg_run_off[si]];
            entcnt += se;
            bool cend = (si + 1 == R.nseg) || (R.seg_c[si + 1] != R.seg_c[si]);
            if (cend || entcnt >= GRP_CAP) {
                R.ncgrp++; R.cgrp_off[R.ncgrp] = si + 1;
                entcnt = 0;
            }
        }
        for (int gi = 0; gi < R.ncgrp; gi++) {
            int s0 = R.cgrp_off[gi];
            R.grp_first[gi] = (s0 == 0 || R.seg_c[s0] != R.seg_c[s0 - 1]) ? 1 : 0;
        }
    }
    return T;
}
constexpr Tab TAB = build_tab();

// ================= template-generated TP products =================
// --- tp0 ---
template<int R, int E, int EEND> struct Ent0T {
    static __device__ __forceinline__ void go(ull va, const char* sbb, ull& t) {
        constexpr int boff = TAB.r[R].ent_b[E] * 256;
        constexpr float cgf = TAB.r[R].ent_cg[E];
        ull vb = *(const ull*)(sbb + boff);
        pfma2(t, pmul2(bcast2(cgf), va), vb);
        Ent0T<R, E + 1, EEND>::go(va, sbb, t);
    }
};
template<int R, int E> struct Ent0T<R, E, E> {
    static __device__ __forceinline__ void go(ull, const char*, ull&) {}
};

template<int R, int RI, int REND> struct Run0T {
    static __device__ __forceinline__ void go(const char* sab, const char* sbb, ull& t) {
        constexpr int aoff = TAB.r[R].run_a[RI] * 256;
        constexpr int e0 = TAB.r[R].run_ent_off[RI];
        constexpr int e1 = TAB.r[R].run_ent_off[RI + 1];
        ull va = *(const ull*)(sab + aoff);
        Ent0T<R, e0, e1>::go(va, sbb, t);
        Run0T<R, RI + 1, REND>::go(sab, sbb, t);
    }
};
template<int R, int RI> struct Run0T<R, RI, RI> {
    static __device__ __forceinline__ void go(const char*, const char*, ull&) {}
};

template<int R, int SI, int SEND> struct Seg0T {
    static __device__ __forceinline__ void go(const char* sab, const char* sbb,
            const float* wq, ull& acc0, ull& acc1) {
        constexpr int s = TAB.r[R].seg_s[SI];
        constexpr int p = TAB.r[R].seg_path[SI];
        constexpr int r0 = TAB.r[R].seg_run_off[SI];
        constexpr int r1 = TAB.r[R].seg_run_off[SI + 1];
        ull t = 0;
        Run0T<R, r0, r1>::go(sab, sbb, t);
        ull W00 = *(const ull*)(wq + p * 256);
        if (s == 0) acc0 = pfma3(W00, t, acc0);
        else        acc1 = pfma3(W00, t, acc1);
        Seg0T<R, SI + 1, SEND>::go(sab, sbb, wq, acc0, acc1);
    }
};
template<int R, int SI> struct Seg0T<R, SI, SI> {
    static __device__ __forceinline__ void go(const char*, const char*,
            const float*, ull&, ull&) {}
};

// capped __noinline__ group bodies: hard walls for register allocation;
// continuation groups read-modify-write the thread-private output slice
template<int R, int GI, int GEND> struct Grp0T {
    static __device__ __noinline__ void body(const char* sab, const char* sbb,
            const float* wq, float* yo) {
        constexpr int s0 = TAB.r[R].cgrp_off[GI];
        constexpr int s1 = TAB.r[R].cgrp_off[GI + 1];
        constexpr int c = TAB.r[R].seg_c[s0];
        constexpr bool first = TAB.r[R].grp_first[GI] != 0;
        ull acc0 = 0, acc1 = 0;
        Seg0T<R, s0, s1>::go(sab, sbb, wq, acc0, acc1);
        float2 r0 = up2(acc0), r1 = up2(acc1);
        if (!first) {
            float2 e = *(float2*)(yo + c * 64);
            float2 o = *(float2*)(yo + (NLM + c) * 64);
            r0.x += e.x; r0.y += e.y; r1.x += o.x; r1.y += o.y;
        }
        *(float2*)(yo + c * 64) = r0;
        *(float2*)(yo + (NLM + c) * 64) = r1;
    }
    static __device__ __forceinline__ void go(const char* sab, const char* sbb,
            const float* wq, float* yo) {
        body(sab, sbb, wq, yo);
        Grp0T<R, GI + 1, GEND>::go(sab, sbb, wq, yo);
    }
};
template<int R, int GI> struct Grp0T<R, GI, GI> {
    static __device__ __forceinline__ void go(const char*, const char*,
            const float*, float*) {}
};

// --- tp1 ---
template<int R, int E, int EEND> struct Ent1T {
    static __device__ __forceinline__ void go(ull a0, ull a1, const char* sbb,
            ull& t00, ull& t01, ull& t10, ull& t11) {
        constexpr int boff = TAB.r[R].ent_b[E] * 512;
        constexpr float cgf = TAB.r[R].ent_cg[E];
        ull cgcg = bcast2(cgf);
        ull b0 = *(const ull*)(sbb + boff);
        ull b1 = *(const ull*)(sbb + boff + 256);
        ull c0 = pmul2(cgcg, a0), c1 = pmul2(cgcg, a1);
        pfma2(t00, c0, b0); pfma2(t01, c0, b1);
        pfma2(t10, c1, b0); pfma2(t11, c1, b1);
        Ent1T<R, E + 1, EEND>::go(a0, a1, sbb, t00, t01, t10, t11);
    }
};
template<int R, int E> struct Ent1T<R, E, E> {
    static __device__ __forceinline__ void go(ull, ull, const char*, ull&, ull&, ull&, ull&) {}
};

template<int R, int RI, int REND> struct Run1T {
    static __device__ __forceinline__ void go(const char* sab, const char* sbb,
            ull& t00, ull& t01, ull& t10, ull& t11) {
        constexpr int aoff = TAB.r[R].run_a[RI] * 512;
        constexpr int e0 = TAB.r[R].run_ent_off[RI];
        constexpr int e1 = TAB.r[R].run_ent_off[RI + 1];
        ull a0 = *(const ull*)(sab + aoff);
        ull a1 = *(const ull*)(sab + aoff + 256);
        Ent1T<R, e0, e1>::go(a0, a1, sbb, t00, t01, t10, t11);
        Run1T<R, RI + 1, REND>::go(sab, sbb, t00, t01, t10, t11);
    }
};
template<int R, int RI> struct Run1T<R, RI, RI> {
    static __device__ __forceinline__ void go(const char*, const char*, ull&, ull&, ull&, ull&) {}
};

template<int R, int SI, int SEND> struct Seg1T {
    static __device__ __forceinline__ void go(const char* sab, const char* sbb,
            const float* wq, ull& acc0, ull& acc1) {
        constexpr int s = TAB.r[R].seg_s[SI];
        constexpr int p = TAB.r[R].seg_path[SI];
        constexpr int r0 = TAB.r[R].seg_run_off[SI];
        constexpr int r1 = TAB.r[R].seg_run_off[SI + 1];
        ull t00 = 0, t01 = 0, t10 = 0, t11 = 0;
        Run1T<R, r0, r1>::go(sab, sbb, t00, t01, t10, t11);
        const float* wpb = wq + p * 256;
        ull W00 = *(const ull*)(wpb);
        ull W01 = *(const ull*)(wpb + 64);
        ull W10 = *(const ull*)(wpb + 128);
        ull W11 = *(const ull*)(wpb + 192);
        ull ev = pfma3(W11, t11, pmul2(W00, t00));
        ull od = pfma3(W10, t10, pmul2(W01, t01));
        if (s == 0) { acc0 = padd2(acc0, ev); acc1 = padd2(acc1, od); }
        else        { acc1 = padd2(acc1, ev); acc0 = padd2(acc0, od); }
        Seg1T<R, SI + 1, SEND>::go(sab, sbb, wq, acc0, acc1);
    }
};
template<int R, int SI> struct Seg1T<R, SI, SI> {
    static __device__ __forceinline__ void go(const char*, const char*,
            const float*, ull&, ull&) {}
};

template<int R, int GI, int GEND> struct Grp1T {
    static __device__ __noinline__ void body(const char* sab, const char* sbb,
            const float* wq, float* yo) {
        constexpr int s0 = TAB.r[R].cgrp_off[GI];
        constexpr int s1 = TAB.r[R].cgrp_off[GI + 1];
        constexpr int c = TAB.r[R].seg_c[s0];
        constexpr bool first = TAB.r[R].grp_first[GI] != 0;
        ull acc0 = 0, acc1 = 0;
        Seg1T<R, s0, s1>::go(sab, sbb, wq, acc0, acc1);
        float2 r0 = up2(acc0), r1 = up2(acc1);
        if (!first) {
            float2 e = *(float2*)(yo + c * 64);
            float2 o = *(float2*)(yo + (NLM + c) * 64);
            r0.x += e.x; r0.y += e.y; r1.x += o.x; r1.y += o.y;
        }
        *(float2*)(yo + c * 64) = r0;
        *(float2*)(yo + (NLM + c) * 64) = r1;
    }
    static __device__ __forceinline__ void go(const char* sab, const char* sbb,
            const float* wq, float* yo) {
        body(sab, sbb, wq, yo);
        Grp1T<R, GI + 1, GEND>::go(sab, sbb, wq, yo);
    }
};
template<int R, int GI> struct Grp1T<R, GI, GI> {
    static __device__ __forceinline__ void go(const char*, const char*,
            const float*, float*) {}
};

// ================= stage kernels =================
__global__ void k_zero(int total4) {
    int t = blockIdx.x * blockDim.x + threadIdx.x;
    if (t < total4) ((float4*)g_y0)[t] = make_float4(0.f, 0.f, 0.f, 0.f);
}

__global__ void k_edge(const int* __restrict__ nbr, const float* __restrict__ disp,
                       const int* __restrict__ Z, const float* __restrict__ Wsp,
                       const float* __restrict__ normp, int E) {
    int t = blockIdx.x * blockDim.x + threadIdx.x;
    int e = t >> 4, lane = t & 15;
    bool valid = (e < E);
    int i = 0, j = 0;
    float dx = 0.f, dy = 0.f, dz = 1.f;
    if (valid) {
        i = nbr[2 * e]; j = nbr[2 * e + 1];
        dx = disp[3 * e]; dy = disp[3 * e + 1]; dz = disp[3 * e + 2];
    }
    float r = sqrtf(dx * dx + dy * dy + dz * dz + 1e-12f);
    float inv = 1.0f / r;
    float x = dx * inv, y = dy * inv, z = dz * inv;
    bool ok = valid && (r < CUTOFF_F);
    float fcut = 0.5f * (cosf(PI_F * fminf(r * (1.0f / CUTOFF_F), 1.0f)) + 1.0f);

    int Zj = valid ? Z[j] : 0;
    const float gamma = 10.24f;
    float d = r - (float)lane * (CUTOFF_F / 15.0f);
    float rbf = expf(-gamma * d * d);

    const float* W = Wsp + Zj * 256 + lane;
    float gsum = 0.0f;
#pragma unroll
    for (int k = 0; k < 16; k++) {
        float rb = __shfl_sync(0xffffffffu, rbf, k, 16);
        gsum = fmaf(rb, W[k * 16], gsum);
    }
    if (!ok) return;
    float g = gsum * fcut / normp[0];

    float x2 = x * x, y2 = y * y, z2 = z * z;
    float Y[NLM];
    Y[0]  = 0.5f * sqrtf(1.0f / PI_F);
    Y[1]  = sqrtf(3.0f / (4.0f * PI_F)) * y;
    Y[2]  = sqrtf(3.0f / (4.0f * PI_F)) * z;
    Y[3]  = sqrtf(3.0f / (4.0f * PI_F)) * x;
    Y[4]  = 0.5f * sqrtf(15.0f / PI_F) * x * y;
    Y[5]  = 0.5f * sqrtf(15.0f / PI_F) * y * z;
    Y[6]  = 0.25f * sqrtf(5.0f / PI_F) * (3.0f * z2 - 1.0f);
    Y[7]  = 0.5f * sqrtf(15.0f / PI_F) * x * z;
    Y[8]  = 0.25f * sqrtf(15.0f / PI_F) * (x2 - y2);
    Y[9]  = 0.25f * sqrtf(35.0f / (2.0f * PI_F)) * y * (3.0f * x2 - y2);
    Y[10] = 0.5f * sqrtf(105.0f / PI_F) * x * y * z;
    Y[11] = 0.25f * sqrtf(21.0f / (2.0f * PI_F)) * y * (5.0f * z2 - 1.0f);
    Y[12] = 0.25f * sqrtf(7.0f / PI_F) * z * (5.0f * z2 - 3.0f);
    Y[13] = 0.25f * sqrtf(21.0f / (2.0f * PI_F)) * x * (5.0f * z2 - 1.0f);
    Y[14] = 0.25f * sqrtf(105.0f / PI_F) * z * (x2 - y2);
    Y[15] = 0.25f * sqrtf(35.0f / (2.0f * PI_F)) * x * (x2 - 3.0f * y2);
    Y[16] = 0.75f * sqrtf(35.0f / PI_F) * x * y * (x2 - y2);
    Y[17] = 0.75f * sqrtf(35.0f / (2.0f * PI_F)) * y * z * (3.0f * x2 - y2);
    Y[18] = 0.75f * sqrtf(5.0f / PI_F) * x * y * (7.0f * z2 - 1.0f);
    Y[19] = 0.75f * sqrtf(5.0f / (2.0f * PI_F)) * y * z * (7.0f * z2 - 3.0f);
    Y[20] = (3.0f / 16.0f) * sqrtf(1.0f / PI_F) * (35.0f * z2 * z2 - 30.0f * z2 + 3.0f);
    Y[21] = 0.75f * sqrtf(5.0f / (2.0f * PI_F)) * x * z * (7.0f * z2 - 3.0f);
    Y[22] = (3.0f / 8.0f) * sqrtf(5.0f / PI_F) * (x2 - y2) * (7.0f * z2 - 1.0f);
    Y[23] = 0.75f * sqrtf(35.0f / (2.0f * PI_F)) * x * z * (x2 - 3.0f * y2);
    Y[24] = (3.0f / 16.0f) * sqrtf(35.0f / PI_F) * (x2 * x2 - 6.0f * x2 * y2 + y2 * y2);

    float* dst = g_y0 + (size_t)i * (NLM * 16) + lane;
#pragma unroll
    for (int lm = 0; lm < NLM; lm++)
        atomicAdd(dst + lm * 16, Y[lm] * g);
}

// ---- TP layer 0 ----
__global__ void __launch_bounds__(128) k_tp0(const float* __restrict__ W1,
                                             const float* __restrict__ W2,
                                             const float* __restrict__ wp) {
    __shared__ __align__(16) float sa[NLM * 64];
    __shared__ __align__(16) float sb[NLM * 64];
    int n = blockIdx.x;
    int tid = threadIdx.x;
    int g = tid & 63;
    int drole = tid >> 6;

    const float* yin = g_y0 + (size_t)n * (NLM * 16);
    const float* Wm = drole ? W2 : W1;
    float* dst = drole ? sb : sa;

    for (int d = 0; d < 5; d++) {
        float w[16];
        const float* Wb = Wm + (d * 16) * 64 + g;
#pragma unroll
        for (int f = 0; f < 16; f++) w[f] = Wb[f * 64];
        for (int lm = d * d; lm < (d + 1) * (d + 1); lm++) {
            const float4* s4 = (const float4*)(yin + lm * 16);
            float a0 = 0.f, a1 = 0.f, a2 = 0.f, a3 = 0.f;
#pragma unroll
            for (int k = 0; k < 4; k++) {
                float4 v = s4[k];
                a0 = fmaf(v.x, w[4*k+0], a0);
                a1 = fmaf(v.y, w[4*k+1], a1);
                a2 = fmaf(v.z, w[4*k+2], a2);
                a3 = fmaf(v.w, w[4*k+3], a3);
            }
            dst[lm * 64 + g] = (a0 + a1) + (a2 + a3);
        }
    }
    __syncthreads();

    int q = tid & 31;
    int role = tid >> 5;
    const char* sab = (const char*)sa + 8 * q;
    const char* sbb = (const char*)sb + 8 * q;
    const float* wq = wp + 2 * q;
    float* yo = g_y1 + (size_t)n * (2 * NLM * 64) + 2 * q;
    if (role == 0)      Grp0T<0, 0, TAB.r[0].ncgrp>::go(sab, sbb, wq, yo);
    else if (role == 1) Grp0T<1, 0, TAB.r[1].ncgrp>::go(sab, sbb, wq, yo);
    else if (role == 2) Grp0T<2, 0, TAB.r[2].ncgrp>::go(sab, sbb, wq, yo);
    else                Grp0T<3, 0, TAB.r[3].ncgrp>::go(sab, sbb, wq, yo);
}

// ---- TP layer 1 ----
__global__ void __launch_bounds__(128) k_tp1(const float* __restrict__ W1,
                                             const float* __restrict__ W2,
                                             const float* __restrict__ wp) {
    __shared__ __align__(16) float sa[NLM * 128];   // [a][p*64 + f] parity-major
    __shared__ __align__(16) float sb[NLM * 128];
    int n = blockIdx.x;
    int tid = threadIdx.x;
    int g = tid & 63;
    int drole = tid >> 6;

    const float* yin = g_y1 + (size_t)n * (2 * NLM * 64);
    const float* Wm = drole ? W2 : W1;
    float* dst = drole ? sb : sa;

    for (int p = 0; p < 2; p++) {
#pragma unroll
        for (int d = 0; d < 5; d++) {
            const int nlm = 2 * d + 1, lm0 = d * d;
            float accA[9], accB[9];
#pragma unroll
            for (int i = 0; i < nlm; i++) { accA[i] = 0.f; accB[i] = 0.f; }
#pragma unroll
            for (int kk = 0; kk < 4; kk++) {
                float w[16];
                const float* Wb = Wm + ((p * 5 + d) * 64 + kk * 16) * 64 + g;
#pragma unroll
                for (int f = 0; f < 16; f++) w[f] = Wb[f * 64];
#pragma unroll
                for (int i = 0; i < nlm; i++) {
                    const float4* s4 = (const float4*)(yin + (p * NLM + lm0 + i) * 64 + kk * 16);
#pragma unroll
                    for (int k2 = 0; k2 < 4; k2++) {
                        float4 v = s4[k2];
                        accA[i] = fmaf(v.x, w[4*k2+0], accA[i]);
                        accB[i] = fmaf(v.y, w[4*k2+1], accB[i]);
                        accA[i] = fmaf(v.z, w[4*k2+2], accA[i]);
                        accB[i] = fmaf(v.w, w[4*k2+3], accB[i]);
                    }
                }
            }
#pragma unroll
            for (int i = 0; i < nlm; i++)
                dst[(lm0 + i) * 128 + p * 64 + g] = accA[i] + accB[i];
        }
    }
    __syncthreads();

    int q = tid & 31;
    int role = tid >> 5;
    const char* sab = (const char*)sa + 8 * q;
    const char* sbb = (const char*)sb + 8 * q;
    const float* wq = wp + 2 * q;
    float* yo = g_y2 + (size_t)n * (2 * NLM * 64) + 2 * q;
    if (role == 0)      Grp1T<0, 0, TAB.r[0].ncgrp>::go(sab, sbb, wq, yo);
    else if (role == 1) Grp1T<1, 0, TAB.r[1].ncgrp>::go(sab, sbb, wq, yo);
    else if (role == 2) Grp1T<2, 0, TAB.r[2].ncgrp>::go(sab, sbb, wq, yo);
    else                Grp1T<3, 0, TAB.r[3].ncgrp>::go(sab, sbb, wq, yo);
}

// ---- final ----
__global__ void __launch_bounds__(160) k_final(const int* __restrict__ Z,
                                               const float* __restrict__ emb,
                                               const float* __restrict__ W_et,
                                               const float* __restrict__ b_et,
                                               const float* __restrict__ wf,
                                               float* __restrict__ outp) {
    __shared__ float s_emb[64];
    int n = blockIdx.x;
    int t = threadIdx.x;
    if (t < 64) s_emb[t] = emb[Z[n] * 64 + t];
    __syncthreads();
    if (t >= 144) return;

    float te = b_et[t];
#pragma unroll
    for (int d = 0; d < 64; d++) te = fmaf(s_emb[d], W_et[d * 144 + t], te);

    for (int p = 0; p < 2; p++) {
        for (int lm = 0; lm < NLM; lm++) {
            float yc;
            if (t < 16)
                yc = (p == 0) ? g_y0[(size_t)n * (NLM * 16) + lm * 16 + t] : 0.0f;
            else if (t < 80)
                yc = g_y1[((size_t)n * 2 + p) * (NLM * 64) + lm * 64 + (t - 16)];
            else
                yc = g_y2[((size_t)n * 2 + p) * (NLM * 64) + lm * 64 + (t - 80)];
            float v = te * yc * wf[(p * 5 + c_deg[lm]) * 144 + t];
            if (p == 0 && lm == 0) v += te;
            float e = expf(fminf(v, 40.0f));
            float u = 1.0f + e;
            float u2 = u * u;
            float o = v * (2.0f * u2) / (u2 + 1.0f);
            outp[(((size_t)n * 2 + p) * NLM + lm) * 144 + t] = o;
        }
    }
}

// ---------------- launch ----------------
extern "C" void kernel_launch(void* const* d_in, const int* in_sizes, int n_in,
                              void* d_out, int out_size) {
    const int*   Z    = (const int*)d_in[0];
    const int*   nbr  = (const int*)d_in[1];
    const float* disp = (const float*)d_in[2];
    const float* Wsp  = (const float*)d_in[3];
    const float* emb  = (const float*)d_in[4];
    const float* W_et = (const float*)d_in[5];
    const float* b_et = (const float*)d_in[6];
    const float* norm = (const float*)d_in[7];
    const float* t0W1 = (const float*)d_in[8];
    const float* t0W2 = (const float*)d_in[9];
    const float* t0wp = (const float*)d_in[10];
    const float* t1W1 = (const float*)d_in[11];
    const float* t1W2 = (const float*)d_in[12];
    const float* t1wp = (const float*)d_in[13];
    const float* wfus = (const float*)d_in[14];
    float* outp = (float*)d_out;

    int N = in_sizes[0];
    int E = in_sizes[1] / 2;

    int tot4 = (N * NLM * 16) / 4;
    k_zero<<<(tot4 + 255) / 256, 256>>>(tot4);                          // 1
    k_edge<<<(E * 16 + 255) / 256, 256>>>(nbr, disp, Z, Wsp, norm, E);  // 2
    k_tp0<<<N, 128>>>(t0W1, t0W2, t0wp);                                // 3
    k_tp1<<<N, 128>>>(t1W1, t1W2, t1wp);                                // 4  <- profiled slot
    k_final<<<N, 160>>>(Z, emb, W_et, b_et, wfus, outp);                // 5
}